// round 1
// baseline (speedup 1.0000x reference)
#include <cuda_runtime.h>
#include <math.h>

#define L      128
#define B      64
#define IN_F   512
#define ACT_F  512
#define H      1024
#define G4     4096      // 4*H
#define LSTM_IN 1024     // IN_F + ACT_F

// ---------------- device scratch (static __device__ arrays; no allocs) ----------------
__device__ float g_gact[(size_t)L * B * G4];  // [L*B, 4H] precomputed input-side gates (incl. biases + input_feature part)
__device__ float g_ginp[B * G4];              // [B, 4H]  input_feature @ W_ii^T + b_ih + b_hh
__device__ float g_gp[4][B * G4];             // K-split partials of h @ W_hh^T
__device__ float g_h[2][B * H];               // double-buffered hidden state
__device__ float g_c[B * H];                  // cell state

__device__ __forceinline__ float sigm(float x) { return 1.0f / (1.0f + expf(-x)); }

// ---------------- init: copy initial h, c ----------------
__global__ void init_state_kernel(const float* __restrict__ h0, const float* __restrict__ c0) {
    int i = blockIdx.x * blockDim.x + threadIdx.x;
    if (i < B * H) {
        g_h[0][i] = h0[i];
        g_c[i]    = c0[i];
    }
}

// ---------------- ginp: [64, 4096] = input_feature @ W_ih[:, :512]^T + b_ih + b_hh ----------------
// grid 32 blocks (n-slices of 128), 256 threads, tile M64 x N128, micro 8x4, BK=16
__global__ void ginp_kernel(const float* __restrict__ inp,
                            const float* __restrict__ W_ih,
                            const float* __restrict__ b_ih,
                            const float* __restrict__ b_hh) {
    __shared__ float aT[16][68];    // aT[kk][b]
    __shared__ float wT[16][132];   // wT[kk][c]
    const int nb0 = blockIdx.x * 128;
    const int tid = threadIdx.x;
    const int tx = tid & 31;        // col within stride group
    const int ty = tid >> 5;        // row group 0..7
    float acc[8][4];
    #pragma unroll
    for (int i = 0; i < 8; i++)
        #pragma unroll
        for (int j = 0; j < 4; j++) acc[i][j] = 0.0f;

    const int lb  = tid >> 2;           // A-load: batch row 0..63
    const int lq  = (tid & 3) * 4;      // A-load: k sub-offset
    const int lc  = tid >> 1;           // W-load: col 0..127
    const int lhf = (tid & 1) * 8;      // W-load: k sub-offset

    for (int k0 = 0; k0 < IN_F; k0 += 16) {
        // load A tile (input_feature rows)
        {
            float4 v = *(const float4*)(inp + lb * IN_F + k0 + lq);
            aT[lq + 0][lb] = v.x; aT[lq + 1][lb] = v.y;
            aT[lq + 2][lb] = v.z; aT[lq + 3][lb] = v.w;
        }
        // load W tile: rows n = nb0 + c, input-part columns k
        {
            const float* wp = W_ih + (size_t)(nb0 + lc) * LSTM_IN + k0 + lhf;
            float4 v0 = *(const float4*)(wp);
            float4 v1 = *(const float4*)(wp + 4);
            wT[lhf + 0][lc] = v0.x; wT[lhf + 1][lc] = v0.y;
            wT[lhf + 2][lc] = v0.z; wT[lhf + 3][lc] = v0.w;
            wT[lhf + 4][lc] = v1.x; wT[lhf + 5][lc] = v1.y;
            wT[lhf + 6][lc] = v1.z; wT[lhf + 7][lc] = v1.w;
        }
        __syncthreads();
        #pragma unroll
        for (int kk = 0; kk < 16; kk++) {
            float av[8];
            float4 u0 = *(const float4*)&aT[kk][ty * 8];
            float4 u1 = *(const float4*)&aT[kk][ty * 8 + 4];
            av[0] = u0.x; av[1] = u0.y; av[2] = u0.z; av[3] = u0.w;
            av[4] = u1.x; av[5] = u1.y; av[6] = u1.z; av[7] = u1.w;
            float wv[4];
            #pragma unroll
            for (int jj = 0; jj < 4; jj++) wv[jj] = wT[kk][tx + 32 * jj];
            #pragma unroll
            for (int i = 0; i < 8; i++)
                #pragma unroll
                for (int jj = 0; jj < 4; jj++) acc[i][jj] += av[i] * wv[jj];
        }
        __syncthreads();
    }
    #pragma unroll
    for (int jj = 0; jj < 4; jj++) {
        int n = nb0 + tx + 32 * jj;
        float bb = b_ih[n] + b_hh[n];
        #pragma unroll
        for (int i = 0; i < 8; i++) {
            int b = ty * 8 + i;
            g_ginp[b * G4 + n] = acc[i][jj] + bb;
        }
    }
}

// ---------------- gact: [8192, 4096] = act @ W_ih[:, 512:]^T + g_ginp (broadcast over t) ----------------
// grid (32 n-blocks, 64 r-blocks), 256 threads, tile 128x128, micro 8x8, BK=16
__global__ void gact_kernel(const float* __restrict__ act,
                            const float* __restrict__ W_ih) {
    __shared__ float aT[16][132];   // aT[kk][row 0..127]
    __shared__ float wT[16][132];   // wT[kk][c 0..127]
    const int nb0 = blockIdx.x * 128;
    const int r0  = blockIdx.y * 128;
    const int tid = threadIdx.x;
    const int tx = tid & 15;        // col group
    const int ty = tid >> 4;        // row group 0..15
    float acc[8][8];
    #pragma unroll
    for (int i = 0; i < 8; i++)
        #pragma unroll
        for (int j = 0; j < 8; j++) acc[i][j] = 0.0f;

    const int lr  = tid >> 1;       // load row/col index 0..127
    const int lhf = (tid & 1) * 8;

    for (int k0 = 0; k0 < ACT_F; k0 += 16) {
        // A tile: act rows
        {
            const float* ap = act + (size_t)(r0 + lr) * ACT_F + k0 + lhf;
            float4 v0 = *(const float4*)(ap);
            float4 v1 = *(const float4*)(ap + 4);
            aT[lhf + 0][lr] = v0.x; aT[lhf + 1][lr] = v0.y;
            aT[lhf + 2][lr] = v0.z; aT[lhf + 3][lr] = v0.w;
            aT[lhf + 4][lr] = v1.x; aT[lhf + 5][lr] = v1.y;
            aT[lhf + 6][lr] = v1.z; aT[lhf + 7][lr] = v1.w;
        }
        // W tile: action-part columns (offset 512)
        {
            const float* wp = W_ih + (size_t)(nb0 + lr) * LSTM_IN + IN_F + k0 + lhf;
            float4 v0 = *(const float4*)(wp);
            float4 v1 = *(const float4*)(wp + 4);
            wT[lhf + 0][lr] = v0.x; wT[lhf + 1][lr] = v0.y;
            wT[lhf + 2][lr] = v0.z; wT[lhf + 3][lr] = v0.w;
            wT[lhf + 4][lr] = v1.x; wT[lhf + 5][lr] = v1.y;
            wT[lhf + 6][lr] = v1.z; wT[lhf + 7][lr] = v1.w;
        }
        __syncthreads();
        #pragma unroll
        for (int kk = 0; kk < 16; kk++) {
            float av[8];
            float4 u0 = *(const float4*)&aT[kk][ty * 8];
            float4 u1 = *(const float4*)&aT[kk][ty * 8 + 4];
            av[0] = u0.x; av[1] = u0.y; av[2] = u0.z; av[3] = u0.w;
            av[4] = u1.x; av[5] = u1.y; av[6] = u1.z; av[7] = u1.w;
            float wv[8];
            #pragma unroll
            for (int jj = 0; jj < 8; jj++) wv[jj] = wT[kk][tx + 16 * jj];
            #pragma unroll
            for (int i = 0; i < 8; i++)
                #pragma unroll
                for (int jj = 0; jj < 8; jj++) acc[i][jj] += av[i] * wv[jj];
        }
        __syncthreads();
    }
    #pragma unroll
    for (int i = 0; i < 8; i++) {
        int r = r0 + ty * 8 + i;
        int b = r & (B - 1);
        #pragma unroll
        for (int jj = 0; jj < 8; jj++) {
            int n = nb0 + tx + 16 * jj;
            g_gact[(size_t)r * G4 + n] = acc[i][jj] + g_ginp[b * G4 + n];
        }
    }
}

// ---------------- r1: per-step recurrent GEMM partials: gp[kp] = h @ W_hh^T (K slice) ----------------
// grid (32 j-slices, 4 k-splits), 256 threads, tile M64 x N128(4 gates x 32 j), micro 8x4, BK=16
__global__ void r1_kernel(const float* __restrict__ W_hh, int t) {
    __shared__ float hT[16][68];
    __shared__ float wT[16][132];
    const int j0 = blockIdx.x * 32;
    const int kp = blockIdx.y;
    const int kb = kp * 256;
    const float* __restrict__ hsrc = g_h[t & 1];
    const int tid = threadIdx.x;
    const int tx = tid & 31;    // j within slice; also gate-col
    const int ty = tid >> 5;    // row group 0..7
    float acc[8][4];
    #pragma unroll
    for (int i = 0; i < 8; i++)
        #pragma unroll
        for (int j = 0; j < 4; j++) acc[i][j] = 0.0f;

    const int lb  = tid >> 2;
    const int lq  = (tid & 3) * 4;
    const int lc  = tid >> 1;                                    // 0..127
    const int lhf = (tid & 1) * 8;
    const int lnr = (lc >> 5) * H + j0 + (lc & 31);              // W_hh row for col lc (x1024 = *H for gates)

    for (int kc = 0; kc < 16; kc++) {
        int k0 = kb + kc * 16;
        {
            float4 v = *(const float4*)(hsrc + lb * H + k0 + lq);
            hT[lq + 0][lb] = v.x; hT[lq + 1][lb] = v.y;
            hT[lq + 2][lb] = v.z; hT[lq + 3][lb] = v.w;
        }
        {
            const float* wp = W_hh + (size_t)((lc >> 5) * H + j0 + (lc & 31)) * H + k0 + lhf;
            float4 v0 = *(const float4*)(wp);
            float4 v1 = *(const float4*)(wp + 4);
            wT[lhf + 0][lc] = v0.x; wT[lhf + 1][lc] = v0.y;
            wT[lhf + 2][lc] = v0.z; wT[lhf + 3][lc] = v0.w;
            wT[lhf + 4][lc] = v1.x; wT[lhf + 5][lc] = v1.y;
            wT[lhf + 6][lc] = v1.z; wT[lhf + 7][lc] = v1.w;
        }
        __syncthreads();
        #pragma unroll
        for (int kk = 0; kk < 16; kk++) {
            float hv[8];
            float4 u0 = *(const float4*)&hT[kk][ty * 8];
            float4 u1 = *(const float4*)&hT[kk][ty * 8 + 4];
            hv[0] = u0.x; hv[1] = u0.y; hv[2] = u0.z; hv[3] = u0.w;
            hv[4] = u1.x; hv[5] = u1.y; hv[6] = u1.z; hv[7] = u1.w;
            float wv[4];
            #pragma unroll
            for (int jj = 0; jj < 4; jj++) wv[jj] = wT[kk][tx + 32 * jj];
            #pragma unroll
            for (int i = 0; i < 8; i++)
                #pragma unroll
                for (int jj = 0; jj < 4; jj++) acc[i][jj] += hv[i] * wv[jj];
        }
        __syncthreads();
    }
    (void)lnr;
    #pragma unroll
    for (int jj = 0; jj < 4; jj++) {
        int n = jj * H + j0 + tx;   // gate jj, column j0+tx
        #pragma unroll
        for (int i = 0; i < 8; i++) {
            int b = ty * 8 + i;
            g_gp[kp][b * G4 + n] = acc[i][jj];
        }
    }
}

// ---------------- r2: reduce partials + LSTM elementwise; writes hs[t], h_next, c ----------------
__global__ void r2_kernel(int t, float* __restrict__ out) {
    int idx = blockIdx.x * blockDim.x + threadIdx.x;   // 0..65535 = b*H + j
    if (idx >= B * H) return;
    int b = idx >> 10;
    int j = idx & (H - 1);
    const float* __restrict__ ga = g_gact + ((size_t)(t * B + b)) * G4;
    float s[4];
    #pragma unroll
    for (int gi = 0; gi < 4; gi++) {
        int n = gi * H + j;
        int bn = b * G4 + n;
        s[gi] = ga[n] + g_gp[0][bn] + g_gp[1][bn] + g_gp[2][bn] + g_gp[3][bn];
    }
    float i_ = sigm(s[0]);
    float f_ = sigm(s[1]);
    float gg = tanhf(s[2]);
    float o_ = sigm(s[3]);
    float c_new = f_ * g_c[idx] + i_ * gg;
    float h_new = o_ * tanhf(c_new);
    g_c[idx] = c_new;
    g_h[(t + 1) & 1][idx] = h_new;
    out[(size_t)t * B * H + idx] = h_new;
}

// ---------------- tail: h_n, c_n appended after hs ----------------
__global__ void tail_kernel(float* __restrict__ out) {
    int idx = blockIdx.x * blockDim.x + threadIdx.x;
    if (idx >= B * H) return;
    out[(size_t)L * B * H + idx]         = g_h[L & 1][idx];  // final hidden (written at t=L-1 into buffer L&1)
    out[(size_t)L * B * H + B * H + idx] = g_c[idx];
}

extern "C" void kernel_launch(void* const* d_in, const int* in_sizes, int n_in,
                              void* d_out, int out_size) {
    const float* inp  = (const float*)d_in[0];  // [B, IN_F]
    const float* act  = (const float*)d_in[1];  // [L, B, ACT_F]
    const float* h0   = (const float*)d_in[2];  // [B, H]
    const float* c0   = (const float*)d_in[3];  // [B, H]
    const float* W_ih = (const float*)d_in[4];  // [4H, LSTM_IN]
    const float* W_hh = (const float*)d_in[5];  // [4H, H]
    const float* b_ih = (const float*)d_in[6];  // [4H]
    const float* b_hh = (const float*)d_in[7];  // [4H]
    float* out = (float*)d_out;
    (void)in_sizes; (void)n_in;

    init_state_kernel<<<(B * H + 255) / 256, 256>>>(h0, c0);
    ginp_kernel<<<32, 256>>>(inp, W_ih, b_ih, b_hh);
    gact_kernel<<<dim3(32, 64), 256>>>(act, W_ih);

    for (int t = 0; t < L; t++) {
        r1_kernel<<<dim3(32, 4), 256>>>(W_hh, t);
        r2_kernel<<<(B * H + 255) / 256, 256>>>(t, out);
    }
    if (out_size >= L * B * H + 2 * B * H) {
        tail_kernel<<<(B * H + 255) / 256, 256>>>(out);
    }
}

// round 3
// speedup vs baseline: 1.2576x; 1.2576x over previous
#include <cuda_runtime.h>
#include <cuda_bf16.h>
#include <stdint.h>
#include <math.h>

#define L      128
#define B      64
#define IN_F   512
#define ACT_F  512
#define H      1024
#define G4     4096
#define LSTM_IN 1024

// tcgen05 is arch-specific: only emit it in passes that target sm_103a/sm_100a
// (feature macros present). Other passes (e.g. a plain compute_103 PTX embed)
// get a correct SIMT fallback body with no tcgen05 mnemonics.
#if defined(__CUDA_ARCH__) && (defined(__CUDA_ARCH_FEAT_SM103_ALL) || defined(__CUDA_ARCH_FEAT_SM100_ALL) || defined(__CUDA_ARCH_SPECIFIC__) || defined(__CUDA_ARCH_FAMILY_SPECIFIC__))
#define HAS_TCGEN05 1
#else
#define HAS_TCGEN05 0
#endif

// ---------------- device scratch ----------------
__device__ float g_gact[(size_t)L * B * G4];   // [t][b][4H] input-side gates (incl all biases + input_feature part)
__device__ float g_ginp[B * G4];               // [b][4H]
__device__ float g_c[B * H];                   // cell state [b][j]
__device__ __nv_bfloat16 g_Whh_hi[G4 * H];     // split-bf16 W_hh
__device__ __nv_bfloat16 g_Whh_lo[G4 * H];
__device__ __nv_bfloat16 g_h_hi[B * H];        // split-bf16 hidden state [b][j]
__device__ __nv_bfloat16 g_h_lo[B * H];

__device__ __forceinline__ float sigm(float x) { return 1.0f / (1.0f + expf(-x)); }

// ---------------- PTX helpers (sm_90-safe ones unconditional) ----------------
__device__ __forceinline__ uint32_t smem_u32(const void* p) {
    uint32_t a;
    asm("{ .reg .u64 t; cvta.to.shared.u64 t, %1; cvt.u32.u64 %0, t; }" : "=r"(a) : "l"(p));
    return a;
}

#define MBARRIER_INIT(addr, cnt) \
    asm volatile("mbarrier.init.shared.b64 [%0], %1;" :: "r"((uint32_t)(addr)), "r"((uint32_t)(cnt)) : "memory")
#define MBARRIER_INVAL(addr) \
    asm volatile("mbarrier.inval.shared.b64 [%0];" :: "r"((uint32_t)(addr)) : "memory")

#define MBARRIER_WAIT_PARITY(mbar_smem_addr, phase_parity) do { \
    uint32_t _mbar = (uint32_t)(mbar_smem_addr); \
    uint32_t _parity = (uint32_t)(phase_parity); \
    uint32_t _done; \
    asm volatile( \
        "{\n\t" \
        ".reg .pred p;\n\t" \
        "mbarrier.try_wait.parity.acquire.cta.shared::cta.b64 p, [%1], %2;\n\t" \
        "selp.b32 %0, 1, 0, p;\n\t" \
        "}" \
        : "=r"(_done) : "r"(_mbar), "r"(_parity) : "memory"); \
    if (!_done) { \
        asm volatile( \
            "{\n\t" \
            ".reg .pred P1;\n\t" \
            "WAIT_LOOP_%=:\n\t" \
            "mbarrier.try_wait.parity.acquire.cta.shared::cta.b64 P1, [%0], %1, 0x989680;\n\t" \
            "@P1 bra.uni WAIT_DONE_%=;\n\t" \
            "bra.uni WAIT_LOOP_%=;\n\t" \
            "WAIT_DONE_%=:\n\t" \
            "}" \
            :: "r"(_mbar), "r"(_parity) : "memory"); \
    } \
} while(0)

#if HAS_TCGEN05
__device__ __forceinline__ uint32_t elect1() {
    uint32_t p;
    asm volatile("{ .reg .pred p; elect.sync _|p, 0xFFFFFFFF; selp.b32 %0, 1, 0, p; }" : "=r"(p));
    return p;
}

#define TCGEN05_ALLOC(smem_result_addr, nCols) \
    asm volatile("tcgen05.alloc.cta_group::1.sync.aligned.shared::cta.b32 [%0], %1;" \
        :: "r"((uint32_t)(smem_result_addr)), "r"((uint32_t)(nCols)) : "memory")
#define TCGEN05_DEALLOC(tmem_addr, nCols) \
    asm volatile("tcgen05.dealloc.cta_group::1.sync.aligned.b32 %0, %1;" :: "r"(tmem_addr), "r"(nCols))
#define TCGEN05_COMMIT(mbar_smem_addr) \
    asm volatile("tcgen05.commit.cta_group::1.mbarrier::arrive::one.shared::cluster.b64 [%0];" \
        :: "r"((uint32_t)(mbar_smem_addr)) : "memory")
#define TCGEN05_FENCE_AFTER() asm volatile("tcgen05.fence::after_thread_sync;" ::: "memory")
#define TCGEN05_FENCE_BEFORE() asm volatile("tcgen05.fence::before_thread_sync;" ::: "memory")
#define TCGEN05_WAIT_LD() asm volatile("tcgen05.wait::ld.sync.aligned;" ::: "memory")
#define FENCE_PROXY_ASYNC_SHARED_CTA() asm volatile("fence.proxy.async.shared::cta;" ::: "memory")

#define TCGEN05_LD_32X32B_X32(r, tmem_addr) \
    asm volatile( \
        "tcgen05.ld.sync.aligned.32x32b.x32.b32 " \
        "{%0, %1, %2, %3, %4, %5, %6, %7, " \
        " %8, %9, %10, %11, %12, %13, %14, %15, " \
        " %16, %17, %18, %19, %20, %21, %22, %23, " \
        " %24, %25, %26, %27, %28, %29, %30, %31}, [%32];" \
        : "=r"((r)[0]),  "=r"((r)[1]),  "=r"((r)[2]),  "=r"((r)[3]), \
          "=r"((r)[4]),  "=r"((r)[5]),  "=r"((r)[6]),  "=r"((r)[7]), \
          "=r"((r)[8]),  "=r"((r)[9]),  "=r"((r)[10]), "=r"((r)[11]), \
          "=r"((r)[12]), "=r"((r)[13]), "=r"((r)[14]), "=r"((r)[15]), \
          "=r"((r)[16]), "=r"((r)[17]), "=r"((r)[18]), "=r"((r)[19]), \
          "=r"((r)[20]), "=r"((r)[21]), "=r"((r)[22]), "=r"((r)[23]), \
          "=r"((r)[24]), "=r"((r)[25]), "=r"((r)[26]), "=r"((r)[27]), \
          "=r"((r)[28]), "=r"((r)[29]), "=r"((r)[30]), "=r"((r)[31]) \
        : "r"(tmem_addr))

__device__ __forceinline__ void mma_bf16_ss(uint32_t d, uint64_t a, uint64_t b,
                                            uint32_t idesc, uint32_t en) {
    asm volatile(
        "{\n\t"
        ".reg .pred p;\n\t"
        "setp.ne.u32 p, %5, 0;\n\t"
        "tcgen05.mma.cta_group::1.kind::f16 [%0], %1, %2, %3, {%4, %4, %4, %4}, p;\n\t"
        "}"
        :: "r"(d), "l"(a), "l"(b), "r"(idesc), "r"(0u), "r"(en) : "memory");
}

// SW128 SMEM descriptor (LBO=1, SBO=64, version=1, layout=SW128)
static __device__ __forceinline__ uint64_t make_desc(uint32_t base) {
    const uint64_t BASE =
        (uint64_t(2) << 61) | (uint64_t(1) << 46) | (uint64_t(64) << 32) | (uint64_t(1) << 16);
    return BASE | ((uint64_t)(base >> 4) & 0x3FFF);
}
#endif // HAS_TCGEN05

__device__ __forceinline__ uint32_t swz(uint32_t x) { return x ^ ((x >> 3) & 0x70); }

// idesc: fp32 accum, bf16 A/B, K-major both, N=64, M=128
#define MMA_IDESC 0x8100490u

// ---------------- SMEM layout for step kernel ----------------
#define SM_TMEM   0
#define SM_MB0    8
#define SM_MB1    16
#define SM_BUF    1024
#define BUF_STRIDE 49152           // 48KB per stage
#define OFF_AHI   0                // 128x64 bf16 = 16KB
#define OFF_ALO   16384
#define OFF_BHI   32768            // 64x64 bf16 = 8KB
#define OFF_BLO   40960
#define SM_G      (1024 + 2 * BUF_STRIDE)      // 99328 : gates, 128 x 68 fp32 = 34816
#define SM_GA     (SM_G + 34816)               // 134144: gact slice, 64 x 136 fp32 = 34816
#define SMEM_TOTAL (SM_GA + 34816)             // 168960

// ---------------- init: c, split h0 ----------------
__global__ void init_state_kernel(const float* __restrict__ h0, const float* __restrict__ c0) {
    int i = blockIdx.x * blockDim.x + threadIdx.x;
    if (i < B * H) {
        g_c[i] = c0[i];
        float h = h0[i];
        __nv_bfloat16 hi = __float2bfloat16(h);
        g_h_hi[i] = hi;
        g_h_lo[i] = __float2bfloat16(h - __bfloat162float(hi));
    }
}

// ---------------- split W_hh into bf16 hi/lo ----------------
__global__ void wsplit_kernel(const float* __restrict__ W) {
    int i = blockIdx.x * blockDim.x + threadIdx.x;
    if (i < G4 * H) {
        float w = W[i];
        __nv_bfloat16 hi = __float2bfloat16(w);
        g_Whh_hi[i] = hi;
        g_Whh_lo[i] = __float2bfloat16(w - __bfloat162float(hi));
    }
}

// ---------------- ginp (fp32) ----------------
__global__ void ginp_kernel(const float* __restrict__ inp,
                            const float* __restrict__ W_ih,
                            const float* __restrict__ b_ih,
                            const float* __restrict__ b_hh) {
    __shared__ float aT[16][68];
    __shared__ float wT[16][132];
    const int nb0 = blockIdx.x * 128;
    const int tid = threadIdx.x;
    const int tx = tid & 31;
    const int ty = tid >> 5;
    float acc[8][4];
    #pragma unroll
    for (int i = 0; i < 8; i++)
        #pragma unroll
        for (int j = 0; j < 4; j++) acc[i][j] = 0.0f;

    const int lb  = tid >> 2;
    const int lq  = (tid & 3) * 4;
    const int lc  = tid >> 1;
    const int lhf = (tid & 1) * 8;

    for (int k0 = 0; k0 < IN_F; k0 += 16) {
        {
            float4 v = *(const float4*)(inp + lb * IN_F + k0 + lq);
            aT[lq + 0][lb] = v.x; aT[lq + 1][lb] = v.y;
            aT[lq + 2][lb] = v.z; aT[lq + 3][lb] = v.w;
        }
        {
            const float* wp = W_ih + (size_t)(nb0 + lc) * LSTM_IN + k0 + lhf;
            float4 v0 = *(const float4*)(wp);
            float4 v1 = *(const float4*)(wp + 4);
            wT[lhf + 0][lc] = v0.x; wT[lhf + 1][lc] = v0.y;
            wT[lhf + 2][lc] = v0.z; wT[lhf + 3][lc] = v0.w;
            wT[lhf + 4][lc] = v1.x; wT[lhf + 5][lc] = v1.y;
            wT[lhf + 6][lc] = v1.z; wT[lhf + 7][lc] = v1.w;
        }
        __syncthreads();
        #pragma unroll
        for (int kk = 0; kk < 16; kk++) {
            float av[8];
            float4 u0 = *(const float4*)&aT[kk][ty * 8];
            float4 u1 = *(const float4*)&aT[kk][ty * 8 + 4];
            av[0] = u0.x; av[1] = u0.y; av[2] = u0.z; av[3] = u0.w;
            av[4] = u1.x; av[5] = u1.y; av[6] = u1.z; av[7] = u1.w;
            float wv[4];
            #pragma unroll
            for (int jj = 0; jj < 4; jj++) wv[jj] = wT[kk][tx + 32 * jj];
            #pragma unroll
            for (int i = 0; i < 8; i++)
                #pragma unroll
                for (int jj = 0; jj < 4; jj++) acc[i][jj] += av[i] * wv[jj];
        }
        __syncthreads();
    }
    #pragma unroll
    for (int jj = 0; jj < 4; jj++) {
        int n = nb0 + tx + 32 * jj;
        float bb = b_ih[n] + b_hh[n];
        #pragma unroll
        for (int i = 0; i < 8; i++) {
            int b = ty * 8 + i;
            g_ginp[b * G4 + n] = acc[i][jj] + bb;
        }
    }
}

// ---------------- gact (fp32) ----------------
__global__ void gact_kernel(const float* __restrict__ act,
                            const float* __restrict__ W_ih) {
    __shared__ float aT[16][132];
    __shared__ float wT[16][132];
    const int nb0 = blockIdx.x * 128;
    const int r0  = blockIdx.y * 128;
    const int tid = threadIdx.x;
    const int tx = tid & 15;
    const int ty = tid >> 4;
    float acc[8][8];
    #pragma unroll
    for (int i = 0; i < 8; i++)
        #pragma unroll
        for (int j = 0; j < 8; j++) acc[i][j] = 0.0f;

    const int lr  = tid >> 1;
    const int lhf = (tid & 1) * 8;

    for (int k0 = 0; k0 < ACT_F; k0 += 16) {
        {
            const float* ap = act + (size_t)(r0 + lr) * ACT_F + k0 + lhf;
            float4 v0 = *(const float4*)(ap);
            float4 v1 = *(const float4*)(ap + 4);
            aT[lhf + 0][lr] = v0.x; aT[lhf + 1][lr] = v0.y;
            aT[lhf + 2][lr] = v0.z; aT[lhf + 3][lr] = v0.w;
            aT[lhf + 4][lr] = v1.x; aT[lhf + 5][lr] = v1.y;
            aT[lhf + 6][lr] = v1.z; aT[lhf + 7][lr] = v1.w;
        }
        {
            const float* wp = W_ih + (size_t)(nb0 + lr) * LSTM_IN + IN_F + k0 + lhf;
            float4 v0 = *(const float4*)(wp);
            float4 v1 = *(const float4*)(wp + 4);
            wT[lhf + 0][lr] = v0.x; wT[lhf + 1][lr] = v0.y;
            wT[lhf + 2][lr] = v0.z; wT[lhf + 3][lr] = v0.w;
            wT[lhf + 4][lr] = v1.x; wT[lhf + 5][lr] = v1.y;
            wT[lhf + 6][lr] = v1.z; wT[lhf + 7][lr] = v1.w;
        }
        __syncthreads();
        #pragma unroll
        for (int kk = 0; kk < 16; kk++) {
            float av[8];
            float4 u0 = *(const float4*)&aT[kk][ty * 8];
            float4 u1 = *(const float4*)&aT[kk][ty * 8 + 4];
            av[0] = u0.x; av[1] = u0.y; av[2] = u0.z; av[3] = u0.w;
            av[4] = u1.x; av[5] = u1.y; av[6] = u1.z; av[7] = u1.w;
            float wv[8];
            #pragma unroll
            for (int jj = 0; jj < 8; jj++) wv[jj] = wT[kk][tx + 16 * jj];
            #pragma unroll
            for (int i = 0; i < 8; i++)
                #pragma unroll
                for (int jj = 0; jj < 8; jj++) acc[i][jj] += av[i] * wv[jj];
        }
        __syncthreads();
    }
    #pragma unroll
    for (int i = 0; i < 8; i++) {
        int r = r0 + ty * 8 + i;
        int b = r & (B - 1);
        #pragma unroll
        for (int jj = 0; jj < 8; jj++) {
            int n = nb0 + tx + 16 * jj;
            g_gact[(size_t)r * G4 + n] = acc[i][jj] + g_ginp[b * G4 + n];
        }
    }
}

// ---------------- common: stage this CTA's gact slice into SMEM ----------------
__device__ __forceinline__ void stage_gact(char* smem, int t, int j0, int tid) {
    const float4* gap = (const float4*)(g_gact + (size_t)t * B * G4);
    float* sga = (float*)(smem + SM_GA);
    #pragma unroll
    for (int i = 0; i < 8; i++) {
        int u = tid + i * 256;               // 0..2047
        int b = u >> 5;
        int rem = u & 31;
        int g = rem >> 3, qq = rem & 7;
        float4 v = gap[(size_t)b * 1024 + g * 256 + (j0 >> 2) + qq];
        *(float4*)(sga + b * 136 + g * 32 + qq * 4) = v;
    }
}

// ---------------- step: recurrent GEMM + fused LSTM epilogue ----------------
// 32 CTAs, each handles j-slice [j0, j0+32). A = gate-stacked W_hh rows (128 x K),
// B = h (64 x K). D[128, 64] = all 4 gates for this slice, all batches.
__global__ void __launch_bounds__(256, 1) step_kernel(int t, const float* __restrict__ Whh,
                                                      float* __restrict__ out) {
    extern __shared__ char smem[];
    uint32_t sb = smem_u32(smem);
    const int tid = threadIdx.x;
    const int wid = tid >> 5;
    const int lid = tid & 31;
    const int j0 = blockIdx.x * 32;

#if HAS_TCGEN05
    if (wid == 0) TCGEN05_ALLOC(sb + SM_TMEM, 128);
    if (tid == 0) { MBARRIER_INIT(sb + SM_MB0, 1); MBARRIER_INIT(sb + SM_MB1, 1); }
    __syncthreads();
    uint32_t tmem;
    asm volatile("ld.shared.b32 %0, [%1];" : "=r"(tmem) : "r"(sb + SM_TMEM));

    const uint4* __restrict__ whi = (const uint4*)g_Whh_hi;   // 8 bf16/uint4, row stride 128 uint4
    const uint4* __restrict__ wlo = (const uint4*)g_Whh_lo;
    const uint4* __restrict__ hhi = (const uint4*)g_h_hi;
    const uint4* __restrict__ hlo = (const uint4*)g_h_lo;

    for (int kc = 0; kc < 16; kc++) {
        const int buf = kc & 1;
        if (kc >= 2) {
            uint32_t mb = sb + (buf ? SM_MB1 : SM_MB0);
            MBARRIER_WAIT_PARITY(mb, ((kc >> 1) - 1) & 1);
        }
        char* bp = smem + SM_BUF + buf * BUF_STRIDE;
        #pragma unroll
        for (int i = 0; i < 4; i++) {
            int u = tid + i * 256;              // 0..1023
            int row = u >> 3, q = u & 7;
            int wrow = ((row >> 5) << 10) + j0 + (row & 31);
            size_t src = (size_t)wrow * 128 + kc * 8 + q;
            uint32_t off = swz(row * 128 + q * 16);
            *(uint4*)(bp + OFF_AHI + off) = whi[src];
            *(uint4*)(bp + OFF_ALO + off) = wlo[src];
        }
        #pragma unroll
        for (int i = 0; i < 2; i++) {
            int u = tid + i * 256;              // 0..511
            int row = u >> 3, q = u & 7;
            size_t src = (size_t)row * 128 + kc * 8 + q;
            uint32_t off = swz(row * 128 + q * 16);
            *(uint4*)(bp + OFF_BHI + off) = hhi[src];
            *(uint4*)(bp + OFF_BLO + off) = hlo[src];
        }
        __syncthreads();
        if (wid == 0) {
            FENCE_PROXY_ASYNC_SHARED_CTA();
            if (elect1()) {
                uint32_t base = sb + SM_BUF + buf * BUF_STRIDE;
                uint64_t ah = make_desc(base + OFF_AHI);
                uint64_t al = make_desc(base + OFF_ALO);
                uint64_t bh = make_desc(base + OFF_BHI);
                uint64_t bl = make_desc(base + OFF_BLO);
                #pragma unroll
                for (int k = 0; k < 4; k++)
                    mma_bf16_ss(tmem, ah + 2 * k, bh + 2 * k, MMA_IDESC, !(kc == 0 && k == 0));
                #pragma unroll
                for (int k = 0; k < 4; k++)
                    mma_bf16_ss(tmem, ah + 2 * k, bl + 2 * k, MMA_IDESC, 1);
                #pragma unroll
                for (int k = 0; k < 4; k++)
                    mma_bf16_ss(tmem, al + 2 * k, bh + 2 * k, MMA_IDESC, 1);
                TCGEN05_COMMIT(sb + (buf ? SM_MB1 : SM_MB0));
            }
        }
    }

    stage_gact(smem, t, j0, tid);   // overlaps tail MMAs

    MBARRIER_WAIT_PARITY(sb + SM_MB0, 1);   // 8th completion on mb0
    MBARRIER_WAIT_PARITY(sb + SM_MB1, 1);   // 8th completion on mb1
    TCGEN05_FENCE_AFTER();

    if (wid < 4) {
        uint32_t dr[64];
        TCGEN05_LD_32X32B_X32(dr, tmem);
        TCGEN05_LD_32X32B_X32(dr + 32, tmem + 32);
        TCGEN05_WAIT_LD();
        TCGEN05_FENCE_BEFORE();
        int r = wid * 32 + lid;                 // gate-stacked row
        float* sg = (float*)(smem + SM_G) + r * 68;
        #pragma unroll
        for (int b2 = 0; b2 < 64; b2++) sg[b2] = __uint_as_float(dr[b2]);
    }
    __syncthreads();
#else
    // ---- SIMT fp32 fallback (no tcgen05 in this compilation pass) ----
    {
        float* sg = (float*)(smem + SM_G);
        float* hs = (float*)(smem + SM_BUF);    // 64 x 132 fp32
        const int r   = tid >> 1;               // 0..127 gate-stacked row
        const int bb0 = (tid & 1) * 32;
        const int wrow = ((r >> 5) << 10) + j0 + (r & 31);
        const float* wp = Whh + (size_t)wrow * H;
        float acc[32];
        #pragma unroll
        for (int i = 0; i < 32; i++) acc[i] = 0.0f;
        for (int kc = 0; kc < 8; kc++) {
            #pragma unroll
            for (int i = 0; i < 32; i++) {
                int u = tid + i * 256;
                int b = u >> 7, k = u & 127;
                int gi = b * H + kc * 128 + k;
                hs[b * 132 + k] = __bfloat162float(g_h_hi[gi]) + __bfloat162float(g_h_lo[gi]);
            }
            __syncthreads();
            for (int k = 0; k < 128; k++) {
                float w = wp[kc * 128 + k];
                #pragma unroll
                for (int i = 0; i < 32; i++)
                    acc[i] += w * hs[(bb0 + i) * 132 + k];
            }
            __syncthreads();
        }
        #pragma unroll
        for (int i = 0; i < 32; i++) sg[r * 68 + bb0 + i] = acc[i];
    }
    stage_gact(smem, t, j0, tid);
    __syncthreads();
#endif

    // ---- LSTM cells: warp w handles batches [8w, 8w+8), lane = j ----
    {
        const float* sg  = (const float*)(smem + SM_G);
        const float* sga = (const float*)(smem + SM_GA);
        int b = wid * 8;
        #pragma unroll
        for (int k = 0; k < 8; k++, b++) {
            float s0 = sga[b * 136 +  0 + lid] + sg[( 0 + lid) * 68 + b];
            float s1 = sga[b * 136 + 32 + lid] + sg[(32 + lid) * 68 + b];
            float s2 = sga[b * 136 + 64 + lid] + sg[(64 + lid) * 68 + b];
            float s3 = sga[b * 136 + 96 + lid] + sg[(96 + lid) * 68 + b];
            int gidx = b * H + j0 + lid;
            float c = g_c[gidx];
            float i_ = sigm(s0);
            float f_ = sigm(s1);
            float gg = tanhf(s2);
            float o_ = sigm(s3);
            float cn = f_ * c + i_ * gg;
            float hn = o_ * tanhf(cn);
            g_c[gidx] = cn;
            out[(size_t)t * B * H + gidx] = hn;
            __nv_bfloat16 hb = __float2bfloat16(hn);
            g_h_hi[gidx] = hb;
            g_h_lo[gidx] = __float2bfloat16(hn - __bfloat162float(hb));
        }
    }

#if HAS_TCGEN05
    __syncthreads();
    if (tid == 0) { MBARRIER_INVAL(sb + SM_MB0); MBARRIER_INVAL(sb + SM_MB1); }
    if (wid == 0) TCGEN05_DEALLOC(tmem, 128);
#endif
}

// ---------------- tail: h_n, c_n ----------------
__global__ void tail_kernel(float* __restrict__ out) {
    int idx = blockIdx.x * blockDim.x + threadIdx.x;
    if (idx >= B * H) return;
    out[(size_t)L * B * H + idx]         = out[(size_t)(L - 1) * B * H + idx];
    out[(size_t)L * B * H + B * H + idx] = g_c[idx];
}

extern "C" void kernel_launch(void* const* d_in, const int* in_sizes, int n_in,
                              void* d_out, int out_size) {
    const float* inp  = (const float*)d_in[0];  // [B, IN_F]
    const float* act  = (const float*)d_in[1];  // [L, B, ACT_F]
    const float* h0   = (const float*)d_in[2];  // [B, H]
    const float* c0   = (const float*)d_in[3];  // [B, H]
    const float* W_ih = (const float*)d_in[4];  // [4H, LSTM_IN]
    const float* W_hh = (const float*)d_in[5];  // [4H, H]
    const float* b_ih = (const float*)d_in[6];  // [4H]
    const float* b_hh = (const float*)d_in[7];  // [4H]
    float* out = (float*)d_out;
    (void)in_sizes; (void)n_in;

    cudaFuncSetAttribute(step_kernel, cudaFuncAttributeMaxDynamicSharedMemorySize, SMEM_TOTAL);

    init_state_kernel<<<(B * H + 255) / 256, 256>>>(h0, c0);
    wsplit_kernel<<<(G4 * H + 255) / 256, 256>>>(W_hh);
    ginp_kernel<<<32, 256>>>(inp, W_ih, b_ih, b_hh);
    gact_kernel<<<dim3(32, 64), 256>>>(act, W_ih);

    for (int t = 0; t < L; t++) {
        step_kernel<<<32, 256, SMEM_TOTAL>>>(t, W_hh, out);
    }
    if (out_size >= L * B * H + 2 * B * H) {
        tail_kernel<<<(B * H + 255) / 256, 256>>>(out);
    }
}

// round 4
// speedup vs baseline: 1.6145x; 1.2838x over previous
#include <cuda_runtime.h>
#include <cuda_bf16.h>
#include <stdint.h>
#include <math.h>

#define L      128
#define B      64
#define IN_F   512
#define ACT_F  512
#define H      1024
#define G4     4096
#define LSTM_IN 1024

#if defined(__CUDA_ARCH__) && (defined(__CUDA_ARCH_FEAT_SM103_ALL) || defined(__CUDA_ARCH_FEAT_SM100_ALL) || defined(__CUDA_ARCH_SPECIFIC__) || defined(__CUDA_ARCH_FAMILY_SPECIFIC__))
#define HAS_TCGEN05 1
#else
#define HAS_TCGEN05 0
#endif

// ---------------- device scratch ----------------
__device__ float g_gact[(size_t)L * B * G4];   // [t][b][4H] input-side gates
__device__ float g_ginp[B * G4];               // [b][4H]
__device__ float g_c[B * H];                   // cell state
__device__ __nv_bfloat16 g_Whh_hi[G4 * H];     // split-bf16 W_hh
__device__ __nv_bfloat16 g_Whh_lo[G4 * H];
__device__ __nv_bfloat16 g_h_hi[B * H];        // split-bf16 hidden state
__device__ __nv_bfloat16 g_h_lo[B * H];
__device__ __nv_bfloat16 g_act_hi[(size_t)L * B * ACT_F];   // split-bf16 action features
__device__ __nv_bfloat16 g_act_lo[(size_t)L * B * ACT_F];
__device__ __nv_bfloat16 g_Wact_hi[G4 * ACT_F];             // split-bf16 W_ih action part
__device__ __nv_bfloat16 g_Wact_lo[G4 * ACT_F];

__device__ __forceinline__ float sigm(float x) { return 1.0f / (1.0f + expf(-x)); }

// ---------------- PTX helpers ----------------
__device__ __forceinline__ uint32_t smem_u32(const void* p) {
    uint32_t a;
    asm("{ .reg .u64 t; cvta.to.shared.u64 t, %1; cvt.u32.u64 %0, t; }" : "=r"(a) : "l"(p));
    return a;
}

#define MBARRIER_INIT(addr, cnt) \
    asm volatile("mbarrier.init.shared.b64 [%0], %1;" :: "r"((uint32_t)(addr)), "r"((uint32_t)(cnt)) : "memory")
#define MBARRIER_INVAL(addr) \
    asm volatile("mbarrier.inval.shared.b64 [%0];" :: "r"((uint32_t)(addr)) : "memory")

#define MBARRIER_WAIT_PARITY(mbar_smem_addr, phase_parity) do { \
    uint32_t _mbar = (uint32_t)(mbar_smem_addr); \
    uint32_t _parity = (uint32_t)(phase_parity); \
    uint32_t _done; \
    asm volatile( \
        "{\n\t" \
        ".reg .pred p;\n\t" \
        "mbarrier.try_wait.parity.acquire.cta.shared::cta.b64 p, [%1], %2;\n\t" \
        "selp.b32 %0, 1, 0, p;\n\t" \
        "}" \
        : "=r"(_done) : "r"(_mbar), "r"(_parity) : "memory"); \
    if (!_done) { \
        asm volatile( \
            "{\n\t" \
            ".reg .pred P1;\n\t" \
            "WAIT_LOOP_%=:\n\t" \
            "mbarrier.try_wait.parity.acquire.cta.shared::cta.b64 P1, [%0], %1, 0x989680;\n\t" \
            "@P1 bra.uni WAIT_DONE_%=;\n\t" \
            "bra.uni WAIT_LOOP_%=;\n\t" \
            "WAIT_DONE_%=:\n\t" \
            "}" \
            :: "r"(_mbar), "r"(_parity) : "memory"); \
    } \
} while(0)

#if HAS_TCGEN05
__device__ __forceinline__ uint32_t elect1() {
    uint32_t p;
    asm volatile("{ .reg .pred p; elect.sync _|p, 0xFFFFFFFF; selp.b32 %0, 1, 0, p; }" : "=r"(p));
    return p;
}

#define TCGEN05_ALLOC(smem_result_addr, nCols) \
    asm volatile("tcgen05.alloc.cta_group::1.sync.aligned.shared::cta.b32 [%0], %1;" \
        :: "r"((uint32_t)(smem_result_addr)), "r"((uint32_t)(nCols)) : "memory")
#define TCGEN05_DEALLOC(tmem_addr, nCols) \
    asm volatile("tcgen05.dealloc.cta_group::1.sync.aligned.b32 %0, %1;" :: "r"(tmem_addr), "r"(nCols))
#define TCGEN05_COMMIT(mbar_smem_addr) \
    asm volatile("tcgen05.commit.cta_group::1.mbarrier::arrive::one.shared::cluster.b64 [%0];" \
        :: "r"((uint32_t)(mbar_smem_addr)) : "memory")
#define TCGEN05_FENCE_AFTER() asm volatile("tcgen05.fence::after_thread_sync;" ::: "memory")
#define TCGEN05_FENCE_BEFORE() asm volatile("tcgen05.fence::before_thread_sync;" ::: "memory")
#define TCGEN05_WAIT_LD() asm volatile("tcgen05.wait::ld.sync.aligned;" ::: "memory")
#define FENCE_PROXY_ASYNC_SHARED_CTA() asm volatile("fence.proxy.async.shared::cta;" ::: "memory")

#define TCGEN05_LD_32X32B_X32(r, tmem_addr) \
    asm volatile( \
        "tcgen05.ld.sync.aligned.32x32b.x32.b32 " \
        "{%0, %1, %2, %3, %4, %5, %6, %7, " \
        " %8, %9, %10, %11, %12, %13, %14, %15, " \
        " %16, %17, %18, %19, %20, %21, %22, %23, " \
        " %24, %25, %26, %27, %28, %29, %30, %31}, [%32];" \
        : "=r"((r)[0]),  "=r"((r)[1]),  "=r"((r)[2]),  "=r"((r)[3]), \
          "=r"((r)[4]),  "=r"((r)[5]),  "=r"((r)[6]),  "=r"((r)[7]), \
          "=r"((r)[8]),  "=r"((r)[9]),  "=r"((r)[10]), "=r"((r)[11]), \
          "=r"((r)[12]), "=r"((r)[13]), "=r"((r)[14]), "=r"((r)[15]), \
          "=r"((r)[16]), "=r"((r)[17]), "=r"((r)[18]), "=r"((r)[19]), \
          "=r"((r)[20]), "=r"((r)[21]), "=r"((r)[22]), "=r"((r)[23]), \
          "=r"((r)[24]), "=r"((r)[25]), "=r"((r)[26]), "=r"((r)[27]), \
          "=r"((r)[28]), "=r"((r)[29]), "=r"((r)[30]), "=r"((r)[31]) \
        : "r"(tmem_addr))

__device__ __forceinline__ void mma_bf16_ss(uint32_t d, uint64_t a, uint64_t b,
                                            uint32_t idesc, uint32_t en) {
    asm volatile(
        "{\n\t"
        ".reg .pred p;\n\t"
        "setp.ne.u32 p, %5, 0;\n\t"
        "tcgen05.mma.cta_group::1.kind::f16 [%0], %1, %2, %3, {%4, %4, %4, %4}, p;\n\t"
        "}"
        :: "r"(d), "l"(a), "l"(b), "r"(idesc), "r"(0u), "r"(en) : "memory");
}

// SW128 SMEM descriptor (LBO=1, SBO=64, version=1, layout=SW128)
static __device__ __forceinline__ uint64_t make_desc(uint32_t base) {
    const uint64_t BASE =
        (uint64_t(2) << 61) | (uint64_t(1) << 46) | (uint64_t(64) << 32) | (uint64_t(1) << 16);
    return BASE | ((uint64_t)(base >> 4) & 0x3FFF);
}
#endif // HAS_TCGEN05

__device__ __forceinline__ uint32_t swz(uint32_t x) { return x ^ ((x >> 3) & 0x70); }

// idesc: fp32 accum, bf16 A/B, K-major, M=128; N=64 and N=256 variants
#define MMA_IDESC_N64  0x8100490u
#define MMA_IDESC_N256 0x8400490u

// ---------------- SMEM layout: step kernel ----------------
#define SM_TMEM   0
#define SM_MB0    8
#define SM_MB1    16
#define SM_BUF    1024
#define BUF_STRIDE 49152
#define OFF_AHI   0
#define OFF_ALO   16384
#define OFF_BHI   32768
#define OFF_BLO   40960
#define SM_G      (1024 + 2 * BUF_STRIDE)
#define SM_GA     (SM_G + 34816)
#define SMEM_TOTAL (SM_GA + 34816)

// ---------------- SMEM layout: gact_tc kernel ----------------
#define GT_STRIDE 98304            // 96KB per stage
#define GT_AHI    0                // 128x64 bf16 = 16KB
#define GT_ALO    16384
#define GT_BHI    32768            // 256x64 bf16 = 32KB
#define GT_BLO    65536
#define GT_SMEM_TOTAL (1024 + 2 * GT_STRIDE)   // 197632

// ---------------- init: c, split h0 ----------------
__global__ void init_state_kernel(const float* __restrict__ h0, const float* __restrict__ c0) {
    int i = blockIdx.x * blockDim.x + threadIdx.x;
    if (i < B * H) {
        g_c[i] = c0[i];
        float h = h0[i];
        __nv_bfloat16 hi = __float2bfloat16(h);
        g_h_hi[i] = hi;
        g_h_lo[i] = __float2bfloat16(h - __bfloat162float(hi));
    }
}

// ---------------- split kernels ----------------
__global__ void wsplit_kernel(const float* __restrict__ W) {
    int i = blockIdx.x * blockDim.x + threadIdx.x;
    if (i < G4 * H) {
        float w = W[i];
        __nv_bfloat16 hi = __float2bfloat16(w);
        g_Whh_hi[i] = hi;
        g_Whh_lo[i] = __float2bfloat16(w - __bfloat162float(hi));
    }
}

__global__ void asplit_kernel(const float* __restrict__ act) {
    int i = blockIdx.x * blockDim.x + threadIdx.x;
    if (i < L * B * ACT_F) {
        float v = act[i];
        __nv_bfloat16 hi = __float2bfloat16(v);
        g_act_hi[i] = hi;
        g_act_lo[i] = __float2bfloat16(v - __bfloat162float(hi));
    }
}

__global__ void wisplit_kernel(const float* __restrict__ W_ih) {
    int i = blockIdx.x * blockDim.x + threadIdx.x;
    if (i < G4 * ACT_F) {
        int n = i >> 9, k = i & 511;
        float w = W_ih[(size_t)n * LSTM_IN + IN_F + k];
        __nv_bfloat16 hi = __float2bfloat16(w);
        g_Wact_hi[i] = hi;
        g_Wact_lo[i] = __float2bfloat16(w - __bfloat162float(hi));
    }
}

// ---------------- ginp (fp32) ----------------
__global__ void ginp_kernel(const float* __restrict__ inp,
                            const float* __restrict__ W_ih,
                            const float* __restrict__ b_ih,
                            const float* __restrict__ b_hh) {
    __shared__ float aT[16][68];
    __shared__ float wT[16][132];
    const int nb0 = blockIdx.x * 128;
    const int tid = threadIdx.x;
    const int tx = tid & 31;
    const int ty = tid >> 5;
    float acc[8][4];
    #pragma unroll
    for (int i = 0; i < 8; i++)
        #pragma unroll
        for (int j = 0; j < 4; j++) acc[i][j] = 0.0f;

    const int lb  = tid >> 2;
    const int lq  = (tid & 3) * 4;
    const int lc  = tid >> 1;
    const int lhf = (tid & 1) * 8;

    for (int k0 = 0; k0 < IN_F; k0 += 16) {
        {
            float4 v = *(const float4*)(inp + lb * IN_F + k0 + lq);
            aT[lq + 0][lb] = v.x; aT[lq + 1][lb] = v.y;
            aT[lq + 2][lb] = v.z; aT[lq + 3][lb] = v.w;
        }
        {
            const float* wp = W_ih + (size_t)(nb0 + lc) * LSTM_IN + k0 + lhf;
            float4 v0 = *(const float4*)(wp);
            float4 v1 = *(const float4*)(wp + 4);
            wT[lhf + 0][lc] = v0.x; wT[lhf + 1][lc] = v0.y;
            wT[lhf + 2][lc] = v0.z; wT[lhf + 3][lc] = v0.w;
            wT[lhf + 4][lc] = v1.x; wT[lhf + 5][lc] = v1.y;
            wT[lhf + 6][lc] = v1.z; wT[lhf + 7][lc] = v1.w;
        }
        __syncthreads();
        #pragma unroll
        for (int kk = 0; kk < 16; kk++) {
            float av[8];
            float4 u0 = *(const float4*)&aT[kk][ty * 8];
            float4 u1 = *(const float4*)&aT[kk][ty * 8 + 4];
            av[0] = u0.x; av[1] = u0.y; av[2] = u0.z; av[3] = u0.w;
            av[4] = u1.x; av[5] = u1.y; av[6] = u1.z; av[7] = u1.w;
            float wv[4];
            #pragma unroll
            for (int jj = 0; jj < 4; jj++) wv[jj] = wT[kk][tx + 32 * jj];
            #pragma unroll
            for (int i = 0; i < 8; i++)
                #pragma unroll
                for (int jj = 0; jj < 4; jj++) acc[i][jj] += av[i] * wv[jj];
        }
        __syncthreads();
    }
    #pragma unroll
    for (int jj = 0; jj < 4; jj++) {
        int n = nb0 + tx + 32 * jj;
        float bb = b_ih[n] + b_hh[n];
        #pragma unroll
        for (int i = 0; i < 8; i++) {
            int b = ty * 8 + i;
            g_ginp[b * G4 + n] = acc[i][jj] + bb;
        }
    }
}

// ---------------- gact_tc: tcgen05 input-side GEMM ----------------
// grid (16 n-tiles of 256, 64 r-tiles of 128). D[m=act row, n=gate col].
__global__ void __launch_bounds__(256, 1) gact_tc_kernel(const float* __restrict__ act,
                                                         const float* __restrict__ W_ih) {
    extern __shared__ char smem[];
    const int tid = threadIdx.x;
    const int n0 = blockIdx.x * 256;
    const int r0 = blockIdx.y * 128;

#if HAS_TCGEN05
    uint32_t sb = smem_u32(smem);
    const int wid = tid >> 5;
    const int lid = tid & 31;

    if (wid == 0) TCGEN05_ALLOC(sb + SM_TMEM, 256);
    if (tid == 0) { MBARRIER_INIT(sb + SM_MB0, 1); MBARRIER_INIT(sb + SM_MB1, 1); }
    __syncthreads();
    uint32_t tmem;
    asm volatile("ld.shared.b32 %0, [%1];" : "=r"(tmem) : "r"(sb + SM_TMEM));

    const uint4* __restrict__ ahi = (const uint4*)g_act_hi;    // row stride 64 uint4 (512 bf16)
    const uint4* __restrict__ alo = (const uint4*)g_act_lo;
    const uint4* __restrict__ whi = (const uint4*)g_Wact_hi;
    const uint4* __restrict__ wlo = (const uint4*)g_Wact_lo;

    for (int kc = 0; kc < 8; kc++) {
        const int buf = kc & 1;
        // prefetch LDGs into registers (overlap with mbarrier wait)
        uint4 aH[4], aL[4], bH[8], bL[8];
        #pragma unroll
        for (int i = 0; i < 4; i++) {
            int u = tid + i * 256;              // 0..1023
            int row = u >> 3, q = u & 7;
            size_t src = (size_t)(r0 + row) * 64 + kc * 8 + q;
            aH[i] = ahi[src]; aL[i] = alo[src];
        }
        #pragma unroll
        for (int i = 0; i < 8; i++) {
            int u = tid + i * 256;              // 0..2047
            int row = u >> 3, q = u & 7;
            size_t src = (size_t)(n0 + row) * 64 + kc * 8 + q;
            bH[i] = whi[src]; bL[i] = wlo[src];
        }
        if (kc >= 2) {
            uint32_t mb = sb + (buf ? SM_MB1 : SM_MB0);
            MBARRIER_WAIT_PARITY(mb, ((kc >> 1) - 1) & 1);
        }
        char* bp = smem + 1024 + buf * GT_STRIDE;
        #pragma unroll
        for (int i = 0; i < 4; i++) {
            int u = tid + i * 256;
            int row = u >> 3, q = u & 7;
            uint32_t off = swz(row * 128 + q * 16);
            *(uint4*)(bp + GT_AHI + off) = aH[i];
            *(uint4*)(bp + GT_ALO + off) = aL[i];
        }
        #pragma unroll
        for (int i = 0; i < 8; i++) {
            int u = tid + i * 256;
            int row = u >> 3, q = u & 7;
            uint32_t off = swz(row * 128 + q * 16);
            *(uint4*)(bp + GT_BHI + off) = bH[i];
            *(uint4*)(bp + GT_BLO + off) = bL[i];
        }
        __syncthreads();
        if (wid == 0) {
            FENCE_PROXY_ASYNC_SHARED_CTA();
            if (elect1()) {
                uint32_t base = sb + 1024 + buf * GT_STRIDE;
                uint64_t ah = make_desc(base + GT_AHI);
                uint64_t al = make_desc(base + GT_ALO);
                uint64_t bh = make_desc(base + GT_BHI);
                uint64_t bl = make_desc(base + GT_BLO);
                #pragma unroll
                for (int k = 0; k < 4; k++)
                    mma_bf16_ss(tmem, ah + 2 * k, bh + 2 * k, MMA_IDESC_N256, !(kc == 0 && k == 0));
                #pragma unroll
                for (int k = 0; k < 4; k++)
                    mma_bf16_ss(tmem, ah + 2 * k, bl + 2 * k, MMA_IDESC_N256, 1);
                #pragma unroll
                for (int k = 0; k < 4; k++)
                    mma_bf16_ss(tmem, al + 2 * k, bh + 2 * k, MMA_IDESC_N256, 1);
                TCGEN05_COMMIT(sb + (buf ? SM_MB1 : SM_MB0));
            }
        }
    }

    MBARRIER_WAIT_PARITY(sb + SM_MB0, 1);   // 4th completion
    MBARRIER_WAIT_PARITY(sb + SM_MB1, 1);
    TCGEN05_FENCE_AFTER();

    if (wid < 4) {
        int m = wid * 32 + lid;
        int r = r0 + m;
        int b = r & (B - 1);
        const float4* gi4 = (const float4*)g_ginp;
        float* outp = g_gact + (size_t)r * G4 + n0;
        #pragma unroll
        for (int cb = 0; cb < 8; cb++) {
            uint32_t dr[32];
            TCGEN05_LD_32X32B_X32(dr, tmem + cb * 32);
            TCGEN05_WAIT_LD();
            #pragma unroll
            for (int q = 0; q < 8; q++) {
                float4 g = gi4[b * (G4 / 4) + (n0 >> 2) + cb * 8 + q];
                float4 v;
                v.x = __uint_as_float(dr[q * 4 + 0]) + g.x;
                v.y = __uint_as_float(dr[q * 4 + 1]) + g.y;
                v.z = __uint_as_float(dr[q * 4 + 2]) + g.z;
                v.w = __uint_as_float(dr[q * 4 + 3]) + g.w;
                *(float4*)(outp + cb * 32 + q * 4) = v;
            }
        }
        TCGEN05_FENCE_BEFORE();
    }
    __syncthreads();
    if (tid == 0) { MBARRIER_INVAL(sb + SM_MB0); MBARRIER_INVAL(sb + SM_MB1); }
    if (wid == 0) TCGEN05_DEALLOC(tmem, 256);
#else
    // naive correct fallback (never executes on GB300: sm_103a SASS is present)
    for (int o = 0; o < 128; o++) {
        int r = r0 + o;
        int n = n0 + tid;
        const float* ap = act + (size_t)r * ACT_F;
        const float* wp = W_ih + (size_t)n * LSTM_IN + IN_F;
        float acc = 0.0f;
        for (int k = 0; k < ACT_F; k++) acc += ap[k] * wp[k];
        g_gact[(size_t)r * G4 + n] = acc + g_ginp[(r & (B - 1)) * G4 + n];
    }
#endif
}

// ---------------- common: stage this CTA's gact slice into SMEM ----------------
__device__ __forceinline__ void stage_gact(char* smem, int t, int j0, int tid) {
    const float4* gap = (const float4*)(g_gact + (size_t)t * B * G4);
    float* sga = (float*)(smem + SM_GA);
    #pragma unroll
    for (int i = 0; i < 8; i++) {
        int u = tid + i * 256;
        int b = u >> 5;
        int rem = u & 31;
        int g = rem >> 3, qq = rem & 7;
        float4 v = gap[(size_t)b * 1024 + g * 256 + (j0 >> 2) + qq];
        *(float4*)(sga + b * 136 + g * 32 + qq * 4) = v;
    }
}

// ---------------- step: recurrent GEMM + fused LSTM epilogue ----------------
__global__ void __launch_bounds__(256, 1) step_kernel(int t, const float* __restrict__ Whh,
                                                      float* __restrict__ out) {
    extern __shared__ char smem[];
    uint32_t sb = smem_u32(smem);
    const int tid = threadIdx.x;
    const int wid = tid >> 5;
    const int lid = tid & 31;
    const int j0 = blockIdx.x * 32;

#if HAS_TCGEN05
    if (wid == 0) TCGEN05_ALLOC(sb + SM_TMEM, 128);
    if (tid == 0) { MBARRIER_INIT(sb + SM_MB0, 1); MBARRIER_INIT(sb + SM_MB1, 1); }
    __syncthreads();
    uint32_t tmem;
    asm volatile("ld.shared.b32 %0, [%1];" : "=r"(tmem) : "r"(sb + SM_TMEM));

    const uint4* __restrict__ whi = (const uint4*)g_Whh_hi;
    const uint4* __restrict__ wlo = (const uint4*)g_Whh_lo;
    const uint4* __restrict__ hhi = (const uint4*)g_h_hi;
    const uint4* __restrict__ hlo = (const uint4*)g_h_lo;

    for (int kc = 0; kc < 16; kc++) {
        const int buf = kc & 1;
        // prefetch LDGs into registers before the mbarrier wait
        uint4 aH[4], aL[4], bH[2], bL[2];
        #pragma unroll
        for (int i = 0; i < 4; i++) {
            int u = tid + i * 256;
            int row = u >> 3, q = u & 7;
            int wrow = ((row >> 5) << 10) + j0 + (row & 31);
            size_t src = (size_t)wrow * 128 + kc * 8 + q;
            aH[i] = whi[src]; aL[i] = wlo[src];
        }
        #pragma unroll
        for (int i = 0; i < 2; i++) {
            int u = tid + i * 256;
            int row = u >> 3, q = u & 7;
            size_t src = (size_t)row * 128 + kc * 8 + q;
            bH[i] = hhi[src]; bL[i] = hlo[src];
        }
        if (kc >= 2) {
            uint32_t mb = sb + (buf ? SM_MB1 : SM_MB0);
            MBARRIER_WAIT_PARITY(mb, ((kc >> 1) - 1) & 1);
        }
        char* bp = smem + SM_BUF + buf * BUF_STRIDE;
        #pragma unroll
        for (int i = 0; i < 4; i++) {
            int u = tid + i * 256;
            int row = u >> 3, q = u & 7;
            uint32_t off = swz(row * 128 + q * 16);
            *(uint4*)(bp + OFF_AHI + off) = aH[i];
            *(uint4*)(bp + OFF_ALO + off) = aL[i];
        }
        #pragma unroll
        for (int i = 0; i < 2; i++) {
            int u = tid + i * 256;
            int row = u >> 3, q = u & 7;
            uint32_t off = swz(row * 128 + q * 16);
            *(uint4*)(bp + OFF_BHI + off) = bH[i];
            *(uint4*)(bp + OFF_BLO + off) = bL[i];
        }
        __syncthreads();
        if (wid == 0) {
            FENCE_PROXY_ASYNC_SHARED_CTA();
            if (elect1()) {
                uint32_t base = sb + SM_BUF + buf * BUF_STRIDE;
                uint64_t ah = make_desc(base + OFF_AHI);
                uint64_t al = make_desc(base + OFF_ALO);
                uint64_t bh = make_desc(base + OFF_BHI);
                uint64_t bl = make_desc(base + OFF_BLO);
                #pragma unroll
                for (int k = 0; k < 4; k++)
                    mma_bf16_ss(tmem, ah + 2 * k, bh + 2 * k, MMA_IDESC_N64, !(kc == 0 && k == 0));
                #pragma unroll
                for (int k = 0; k < 4; k++)
                    mma_bf16_ss(tmem, ah + 2 * k, bl + 2 * k, MMA_IDESC_N64, 1);
                #pragma unroll
                for (int k = 0; k < 4; k++)
                    mma_bf16_ss(tmem, al + 2 * k, bh + 2 * k, MMA_IDESC_N64, 1);
                TCGEN05_COMMIT(sb + (buf ? SM_MB1 : SM_MB0));
            }
        }
    }

    stage_gact(smem, t, j0, tid);   // overlaps tail MMAs

    MBARRIER_WAIT_PARITY(sb + SM_MB0, 1);
    MBARRIER_WAIT_PARITY(sb + SM_MB1, 1);
    TCGEN05_FENCE_AFTER();

    if (wid < 4) {
        uint32_t dr[64];
        TCGEN05_LD_32X32B_X32(dr, tmem);
        TCGEN05_LD_32X32B_X32(dr + 32, tmem + 32);
        TCGEN05_WAIT_LD();
        TCGEN05_FENCE_BEFORE();
        int r = wid * 32 + lid;
        float* sg = (float*)(smem + SM_G) + r * 68;
        #pragma unroll
        for (int b2 = 0; b2 < 64; b2++) sg[b2] = __uint_as_float(dr[b2]);
    }
    __syncthreads();
#else
    // ---- SIMT fp32 fallback ----
    {
        float* sg = (float*)(smem + SM_G);
        float* hs = (float*)(smem + SM_BUF);
        const int r   = tid >> 1;
        const int bb0 = (tid & 1) * 32;
        const int wrow = ((r >> 5) << 10) + j0 + (r & 31);
        const float* wp = Whh + (size_t)wrow * H;
        float acc[32];
        #pragma unroll
        for (int i = 0; i < 32; i++) acc[i] = 0.0f;
        for (int kc = 0; kc < 8; kc++) {
            #pragma unroll
            for (int i = 0; i < 32; i++) {
                int u = tid + i * 256;
                int b = u >> 7, k = u & 127;
                int gi = b * H + kc * 128 + k;
                hs[b * 132 + k] = __bfloat162float(g_h_hi[gi]) + __bfloat162float(g_h_lo[gi]);
            }
            __syncthreads();
            for (int k = 0; k < 128; k++) {
                float w = wp[kc * 128 + k];
                #pragma unroll
                for (int i = 0; i < 32; i++)
                    acc[i] += w * hs[(bb0 + i) * 132 + k];
            }
            __syncthreads();
        }
        #pragma unroll
        for (int i = 0; i < 32; i++) sg[r * 68 + bb0 + i] = acc[i];
    }
    stage_gact(smem, t, j0, tid);
    __syncthreads();
#endif

    // ---- LSTM cells ----
    {
        const float* sg  = (const float*)(smem + SM_G);
        const float* sga = (const float*)(smem + SM_GA);
        int b = wid * 8;
        #pragma unroll
        for (int k = 0; k < 8; k++, b++) {
            float s0 = sga[b * 136 +  0 + lid] + sg[( 0 + lid) * 68 + b];
            float s1 = sga[b * 136 + 32 + lid] + sg[(32 + lid) * 68 + b];
            float s2 = sga[b * 136 + 64 + lid] + sg[(64 + lid) * 68 + b];
            float s3 = sga[b * 136 + 96 + lid] + sg[(96 + lid) * 68 + b];
            int gidx = b * H + j0 + lid;
            float c = g_c[gidx];
            float i_ = sigm(s0);
            float f_ = sigm(s1);
            float gg = tanhf(s2);
            float o_ = sigm(s3);
            float cn = f_ * c + i_ * gg;
            float hn = o_ * tanhf(cn);
            g_c[gidx] = cn;
            out[(size_t)t * B * H + gidx] = hn;
            __nv_bfloat16 hb = __float2bfloat16(hn);
            g_h_hi[gidx] = hb;
            g_h_lo[gidx] = __float2bfloat16(hn - __bfloat162float(hb));
        }
    }

#if HAS_TCGEN05
    __syncthreads();
    if (tid == 0) { MBARRIER_INVAL(sb + SM_MB0); MBARRIER_INVAL(sb + SM_MB1); }
    if (wid == 0) TCGEN05_DEALLOC(tmem, 128);
#endif
}

// ---------------- tail: h_n, c_n ----------------
__global__ void tail_kernel(float* __restrict__ out) {
    int idx = blockIdx.x * blockDim.x + threadIdx.x;
    if (idx >= B * H) return;
    out[(size_t)L * B * H + idx]         = out[(size_t)(L - 1) * B * H + idx];
    out[(size_t)L * B * H + B * H + idx] = g_c[idx];
}

extern "C" void kernel_launch(void* const* d_in, const int* in_sizes, int n_in,
                              void* d_out, int out_size) {
    const float* inp  = (const float*)d_in[0];
    const float* act  = (const float*)d_in[1];
    const float* h0   = (const float*)d_in[2];
    const float* c0   = (const float*)d_in[3];
    const float* W_ih = (const float*)d_in[4];
    const float* W_hh = (const float*)d_in[5];
    const float* b_ih = (const float*)d_in[6];
    const float* b_hh = (const float*)d_in[7];
    float* out = (float*)d_out;
    (void)in_sizes; (void)n_in;

    cudaFuncSetAttribute(step_kernel, cudaFuncAttributeMaxDynamicSharedMemorySize, SMEM_TOTAL);
    cudaFuncSetAttribute(gact_tc_kernel, cudaFuncAttributeMaxDynamicSharedMemorySize, GT_SMEM_TOTAL);

    init_state_kernel<<<(B * H + 255) / 256, 256>>>(h0, c0);
    wsplit_kernel<<<(G4 * H + 255) / 256, 256>>>(W_hh);
    asplit_kernel<<<(L * B * ACT_F + 255) / 256, 256>>>(act);
    wisplit_kernel<<<(G4 * ACT_F + 255) / 256, 256>>>(W_ih);
    ginp_kernel<<<32, 256>>>(inp, W_ih, b_ih, b_hh);
    gact_tc_kernel<<<dim3(16, 64), 256, GT_SMEM_TOTAL>>>(act, W_ih);

    for (int t = 0; t < L; t++) {
        step_kernel<<<32, 256, SMEM_TOTAL>>>(t, W_hh, out);
    }
    if (out_size >= L * B * H + 2 * B * H) {
        tail_kernel<<<(B * H + 255) / 256, 256>>>(out);
    }
}

// round 5
// speedup vs baseline: 1.9543x; 1.2105x over previous
#include <cuda_runtime.h>
#include <cuda_bf16.h>
#include <stdint.h>
#include <math.h>

#define L      128
#define B      64
#define IN_F   512
#define ACT_F  512
#define H      1024
#define G4     4096
#define LSTM_IN 1024

#if defined(__CUDA_ARCH__) && (defined(__CUDA_ARCH_FEAT_SM103_ALL) || defined(__CUDA_ARCH_FEAT_SM100_ALL) || defined(__CUDA_ARCH_SPECIFIC__) || defined(__CUDA_ARCH_FAMILY_SPECIFIC__))
#define HAS_TCGEN05 1
#else
#define HAS_TCGEN05 0
#endif

// ---------------- device scratch ----------------
__device__ float g_gact[(size_t)L * B * G4];   // [t][b][4H] input-side gates
__device__ float g_ginp[B * G4];               // [b][4H]
__device__ float g_c[B * H];                   // cell state
__device__ __nv_bfloat16 g_Whh_hi[G4 * H];     // split-bf16 W_hh
__device__ __nv_bfloat16 g_Whh_lo[G4 * H];
__device__ __nv_bfloat16 g_h_hi[2][B * H];     // double-buffered split-bf16 hidden state
__device__ __nv_bfloat16 g_h_lo[2][B * H];
__device__ __nv_bfloat16 g_act_hi[(size_t)L * B * ACT_F];
__device__ __nv_bfloat16 g_act_lo[(size_t)L * B * ACT_F];
__device__ __nv_bfloat16 g_Wact_hi[G4 * ACT_F];
__device__ __nv_bfloat16 g_Wact_lo[G4 * ACT_F];
__device__ unsigned g_bar;                     // persistent-kernel step barrier

__device__ __forceinline__ float sigm(float x) { return 1.0f / (1.0f + expf(-x)); }

// ---------------- PTX helpers ----------------
__device__ __forceinline__ uint32_t smem_u32(const void* p) {
    uint32_t a;
    asm("{ .reg .u64 t; cvta.to.shared.u64 t, %1; cvt.u32.u64 %0, t; }" : "=r"(a) : "l"(p));
    return a;
}

// cp.async (sm_80+, safe in all passes)
#define CP_ASYNC16(dst, src) \
    asm volatile("cp.async.cg.shared.global [%0], [%1], 16;" :: "r"((uint32_t)(dst)), "l"(src) : "memory")
#define CP_COMMIT() asm volatile("cp.async.commit_group;" ::: "memory")
#define CP_WAIT(n)  asm volatile("cp.async.wait_group %0;" :: "n"(n) : "memory")

#define MBARRIER_INIT(addr, cnt) \
    asm volatile("mbarrier.init.shared.b64 [%0], %1;" :: "r"((uint32_t)(addr)), "r"((uint32_t)(cnt)) : "memory")
#define MBARRIER_INVAL(addr) \
    asm volatile("mbarrier.inval.shared.b64 [%0];" :: "r"((uint32_t)(addr)) : "memory")

#define MBARRIER_WAIT_PARITY(mbar_smem_addr, phase_parity) do { \
    uint32_t _mbar = (uint32_t)(mbar_smem_addr); \
    uint32_t _parity = (uint32_t)(phase_parity); \
    uint32_t _done; \
    asm volatile( \
        "{\n\t" \
        ".reg .pred p;\n\t" \
        "mbarrier.try_wait.parity.acquire.cta.shared::cta.b64 p, [%1], %2;\n\t" \
        "selp.b32 %0, 1, 0, p;\n\t" \
        "}" \
        : "=r"(_done) : "r"(_mbar), "r"(_parity) : "memory"); \
    if (!_done) { \
        asm volatile( \
            "{\n\t" \
            ".reg .pred P1;\n\t" \
            "WAIT_LOOP_%=:\n\t" \
            "mbarrier.try_wait.parity.acquire.cta.shared::cta.b64 P1, [%0], %1, 0x989680;\n\t" \
            "@P1 bra.uni WAIT_DONE_%=;\n\t" \
            "bra.uni WAIT_LOOP_%=;\n\t" \
            "WAIT_DONE_%=:\n\t" \
            "}" \
            :: "r"(_mbar), "r"(_parity) : "memory"); \
    } \
} while(0)

#if HAS_TCGEN05
__device__ __forceinline__ uint32_t elect1() {
    uint32_t p;
    asm volatile("{ .reg .pred p; elect.sync _|p, 0xFFFFFFFF; selp.b32 %0, 1, 0, p; }" : "=r"(p));
    return p;
}

#define TCGEN05_ALLOC(smem_result_addr, nCols) \
    asm volatile("tcgen05.alloc.cta_group::1.sync.aligned.shared::cta.b32 [%0], %1;" \
        :: "r"((uint32_t)(smem_result_addr)), "r"((uint32_t)(nCols)) : "memory")
#define TCGEN05_DEALLOC(tmem_addr, nCols) \
    asm volatile("tcgen05.dealloc.cta_group::1.sync.aligned.b32 %0, %1;" :: "r"(tmem_addr), "r"(nCols))
#define TCGEN05_COMMIT(mbar_smem_addr) \
    asm volatile("tcgen05.commit.cta_group::1.mbarrier::arrive::one.shared::cluster.b64 [%0];" \
        :: "r"((uint32_t)(mbar_smem_addr)) : "memory")
#define TCGEN05_FENCE_AFTER() asm volatile("tcgen05.fence::after_thread_sync;" ::: "memory")
#define TCGEN05_FENCE_BEFORE() asm volatile("tcgen05.fence::before_thread_sync;" ::: "memory")
#define TCGEN05_WAIT_LD() asm volatile("tcgen05.wait::ld.sync.aligned;" ::: "memory")
#define FENCE_PROXY_ASYNC_SHARED_CTA() asm volatile("fence.proxy.async.shared::cta;" ::: "memory")

#define TCGEN05_LD_32X32B_X32(r, tmem_addr) \
    asm volatile( \
        "tcgen05.ld.sync.aligned.32x32b.x32.b32 " \
        "{%0, %1, %2, %3, %4, %5, %6, %7, " \
        " %8, %9, %10, %11, %12, %13, %14, %15, " \
        " %16, %17, %18, %19, %20, %21, %22, %23, " \
        " %24, %25, %26, %27, %28, %29, %30, %31}, [%32];" \
        : "=r"((r)[0]),  "=r"((r)[1]),  "=r"((r)[2]),  "=r"((r)[3]), \
          "=r"((r)[4]),  "=r"((r)[5]),  "=r"((r)[6]),  "=r"((r)[7]), \
          "=r"((r)[8]),  "=r"((r)[9]),  "=r"((r)[10]), "=r"((r)[11]), \
          "=r"((r)[12]), "=r"((r)[13]), "=r"((r)[14]), "=r"((r)[15]), \
          "=r"((r)[16]), "=r"((r)[17]), "=r"((r)[18]), "=r"((r)[19]), \
          "=r"((r)[20]), "=r"((r)[21]), "=r"((r)[22]), "=r"((r)[23]), \
          "=r"((r)[24]), "=r"((r)[25]), "=r"((r)[26]), "=r"((r)[27]), \
          "=r"((r)[28]), "=r"((r)[29]), "=r"((r)[30]), "=r"((r)[31]) \
        : "r"(tmem_addr))

__device__ __forceinline__ void mma_bf16_ss(uint32_t d, uint64_t a, uint64_t b,
                                            uint32_t idesc, uint32_t en) {
    asm volatile(
        "{\n\t"
        ".reg .pred p;\n\t"
        "setp.ne.u32 p, %5, 0;\n\t"
        "tcgen05.mma.cta_group::1.kind::f16 [%0], %1, %2, %3, {%4, %4, %4, %4}, p;\n\t"
        "}"
        :: "r"(d), "l"(a), "l"(b), "r"(idesc), "r"(0u), "r"(en) : "memory");
}

static __device__ __forceinline__ uint64_t make_desc(uint32_t base) {
    const uint64_t BASE =
        (uint64_t(2) << 61) | (uint64_t(1) << 46) | (uint64_t(64) << 32) | (uint64_t(1) << 16);
    return BASE | ((uint64_t)(base >> 4) & 0x3FFF);
}
#endif // HAS_TCGEN05

__device__ __forceinline__ uint32_t swz(uint32_t x) { return x ^ ((x >> 3) & 0x70); }

#define MMA_IDESC_N64  0x8100490u
#define MMA_IDESC_N256 0x8400490u

// ---------------- SMEM layout: persistent decoder ----------------
#define SM_TMEM   0
#define SM_MB0    8
#define SM_MB1    16
#define SM_BUF    1024
#define BUF_STRIDE 49152
#define OFF_AHI   0
#define OFF_ALO   16384
#define OFF_BHI   32768
#define OFF_BLO   40960
#define SM_G      (1024 + 2 * BUF_STRIDE)
#define SM_GA     (SM_G + 34816)
#define SMEM_TOTAL (SM_GA + 34816)

// ---------------- SMEM layout: gact_tc kernel ----------------
#define GT_STRIDE 98304
#define GT_AHI    0
#define GT_ALO    16384
#define GT_BHI    32768
#define GT_BLO    65536
#define GT_SMEM_TOTAL (1024 + 2 * GT_STRIDE)

// ---------------- init: c, h0 split, barrier reset ----------------
__global__ void init_state_kernel(const float* __restrict__ h0, const float* __restrict__ c0) {
    int i = blockIdx.x * blockDim.x + threadIdx.x;
    if (i == 0) g_bar = 0;                 // reset step barrier each replay
    if (i < B * H) {
        g_c[i] = c0[i];
        float h = h0[i];
        __nv_bfloat16 hi = __float2bfloat16(h);
        g_h_hi[0][i] = hi;
        g_h_lo[0][i] = __float2bfloat16(h - __bfloat162float(hi));
    }
}

// ---------------- split kernels ----------------
__global__ void wsplit_kernel(const float* __restrict__ W) {
    int i = blockIdx.x * blockDim.x + threadIdx.x;
    if (i < G4 * H) {
        float w = W[i];
        __nv_bfloat16 hi = __float2bfloat16(w);
        g_Whh_hi[i] = hi;
        g_Whh_lo[i] = __float2bfloat16(w - __bfloat162float(hi));
    }
}

__global__ void asplit_kernel(const float* __restrict__ act) {
    int i = blockIdx.x * blockDim.x + threadIdx.x;
    if (i < L * B * ACT_F) {
        float v = act[i];
        __nv_bfloat16 hi = __float2bfloat16(v);
        g_act_hi[i] = hi;
        g_act_lo[i] = __float2bfloat16(v - __bfloat162float(hi));
    }
}

__global__ void wisplit_kernel(const float* __restrict__ W_ih) {
    int i = blockIdx.x * blockDim.x + threadIdx.x;
    if (i < G4 * ACT_F) {
        int n = i >> 9, k = i & 511;
        float w = W_ih[(size_t)n * LSTM_IN + IN_F + k];
        __nv_bfloat16 hi = __float2bfloat16(w);
        g_Wact_hi[i] = hi;
        g_Wact_lo[i] = __float2bfloat16(w - __bfloat162float(hi));
    }
}

// ---------------- ginp (fp32) ----------------
__global__ void ginp_kernel(const float* __restrict__ inp,
                            const float* __restrict__ W_ih,
                            const float* __restrict__ b_ih,
                            const float* __restrict__ b_hh) {
    __shared__ float aT[16][68];
    __shared__ float wT[16][132];
    const int nb0 = blockIdx.x * 128;
    const int tid = threadIdx.x;
    const int tx = tid & 31;
    const int ty = tid >> 5;
    float acc[8][4];
    #pragma unroll
    for (int i = 0; i < 8; i++)
        #pragma unroll
        for (int j = 0; j < 4; j++) acc[i][j] = 0.0f;

    const int lb  = tid >> 2;
    const int lq  = (tid & 3) * 4;
    const int lc  = tid >> 1;
    const int lhf = (tid & 1) * 8;

    for (int k0 = 0; k0 < IN_F; k0 += 16) {
        {
            float4 v = *(const float4*)(inp + lb * IN_F + k0 + lq);
            aT[lq + 0][lb] = v.x; aT[lq + 1][lb] = v.y;
            aT[lq + 2][lb] = v.z; aT[lq + 3][lb] = v.w;
        }
        {
            const float* wp = W_ih + (size_t)(nb0 + lc) * LSTM_IN + k0 + lhf;
            float4 v0 = *(const float4*)(wp);
            float4 v1 = *(const float4*)(wp + 4);
            wT[lhf + 0][lc] = v0.x; wT[lhf + 1][lc] = v0.y;
            wT[lhf + 2][lc] = v0.z; wT[lhf + 3][lc] = v0.w;
            wT[lhf + 4][lc] = v1.x; wT[lhf + 5][lc] = v1.y;
            wT[lhf + 6][lc] = v1.z; wT[lhf + 7][lc] = v1.w;
        }
        __syncthreads();
        #pragma unroll
        for (int kk = 0; kk < 16; kk++) {
            float av[8];
            float4 u0 = *(const float4*)&aT[kk][ty * 8];
            float4 u1 = *(const float4*)&aT[kk][ty * 8 + 4];
            av[0] = u0.x; av[1] = u0.y; av[2] = u0.z; av[3] = u0.w;
            av[4] = u1.x; av[5] = u1.y; av[6] = u1.z; av[7] = u1.w;
            float wv[4];
            #pragma unroll
            for (int jj = 0; jj < 4; jj++) wv[jj] = wT[kk][tx + 32 * jj];
            #pragma unroll
            for (int i = 0; i < 8; i++)
                #pragma unroll
                for (int jj = 0; jj < 4; jj++) acc[i][jj] += av[i] * wv[jj];
        }
        __syncthreads();
    }
    #pragma unroll
    for (int jj = 0; jj < 4; jj++) {
        int n = nb0 + tx + 32 * jj;
        float bb = b_ih[n] + b_hh[n];
        #pragma unroll
        for (int i = 0; i < 8; i++) {
            int b = ty * 8 + i;
            g_ginp[b * G4 + n] = acc[i][jj] + bb;
        }
    }
}

// ---------------- gact_tc: tcgen05 input-side GEMM ----------------
__global__ void __launch_bounds__(256, 1) gact_tc_kernel(const float* __restrict__ act,
                                                         const float* __restrict__ W_ih) {
    extern __shared__ char smem[];
    const int tid = threadIdx.x;
    const int n0 = blockIdx.x * 256;
    const int r0 = blockIdx.y * 128;

#if HAS_TCGEN05
    uint32_t sb = smem_u32(smem);
    const int wid = tid >> 5;
    const int lid = tid & 31;

    if (wid == 0) TCGEN05_ALLOC(sb + SM_TMEM, 256);
    if (tid == 0) { MBARRIER_INIT(sb + SM_MB0, 1); MBARRIER_INIT(sb + SM_MB1, 1); }
    __syncthreads();
    uint32_t tmem;
    asm volatile("ld.shared.b32 %0, [%1];" : "=r"(tmem) : "r"(sb + SM_TMEM));

    const char* ahi = (const char*)g_act_hi;
    const char* alo = (const char*)g_act_lo;
    const char* whi = (const char*)g_Wact_hi;
    const char* wlo = (const char*)g_Wact_lo;

    for (int kc = 0; kc < 8; kc++) {
        const int buf = kc & 1;
        if (kc >= 2) {
            uint32_t mb = sb + (buf ? SM_MB1 : SM_MB0);
            MBARRIER_WAIT_PARITY(mb, ((kc >> 1) - 1) & 1);
        }
        uint32_t base = sb + 1024 + buf * GT_STRIDE;
        #pragma unroll
        for (int i = 0; i < 4; i++) {
            int u = tid + i * 256;
            int row = u >> 3, q = u & 7;
            size_t so = ((size_t)(r0 + row) * 64 + kc * 8 + q) * 16;
            uint32_t d = base + GT_AHI + swz(row * 128 + q * 16);
            CP_ASYNC16(d, ahi + so);
            CP_ASYNC16(d + (GT_ALO - GT_AHI), alo + so);
        }
        #pragma unroll
        for (int i = 0; i < 8; i++) {
            int u = tid + i * 256;
            int row = u >> 3, q = u & 7;
            size_t so = ((size_t)(n0 + row) * 64 + kc * 8 + q) * 16;
            uint32_t d = base + GT_BHI + swz(row * 128 + q * 16);
            CP_ASYNC16(d, whi + so);
            CP_ASYNC16(d + (GT_BLO - GT_BHI), wlo + so);
        }
        CP_COMMIT();
        if (kc >= 1) {
            CP_WAIT(1);
            __syncthreads();
            if (wid == 0) {
                FENCE_PROXY_ASYNC_SHARED_CTA();
                if (elect1()) {
                    int j = kc - 1;
                    uint32_t b2 = sb + 1024 + (j & 1) * GT_STRIDE;
                    uint64_t ah = make_desc(b2 + GT_AHI);
                    uint64_t al = make_desc(b2 + GT_ALO);
                    uint64_t bh = make_desc(b2 + GT_BHI);
                    uint64_t bl = make_desc(b2 + GT_BLO);
                    #pragma unroll
                    for (int k = 0; k < 4; k++)
                        mma_bf16_ss(tmem, ah + 2 * k, bh + 2 * k, MMA_IDESC_N256, !(j == 0 && k == 0));
                    #pragma unroll
                    for (int k = 0; k < 4; k++)
                        mma_bf16_ss(tmem, ah + 2 * k, bl + 2 * k, MMA_IDESC_N256, 1);
                    #pragma unroll
                    for (int k = 0; k < 4; k++)
                        mma_bf16_ss(tmem, al + 2 * k, bh + 2 * k, MMA_IDESC_N256, 1);
                    TCGEN05_COMMIT(sb + ((j & 1) ? SM_MB1 : SM_MB0));
                }
            }
        }
    }
    // tail chunk 7
    CP_WAIT(0);
    __syncthreads();
    if (wid == 0) {
        FENCE_PROXY_ASYNC_SHARED_CTA();
        if (elect1()) {
            uint32_t b2 = sb + 1024 + GT_STRIDE;   // buf 1 (chunk 7)
            uint64_t ah = make_desc(b2 + GT_AHI);
            uint64_t al = make_desc(b2 + GT_ALO);
            uint64_t bh = make_desc(b2 + GT_BHI);
            uint64_t bl = make_desc(b2 + GT_BLO);
            #pragma unroll
            for (int k = 0; k < 4; k++)
                mma_bf16_ss(tmem, ah + 2 * k, bh + 2 * k, MMA_IDESC_N256, 1);
            #pragma unroll
            for (int k = 0; k < 4; k++)
                mma_bf16_ss(tmem, ah + 2 * k, bl + 2 * k, MMA_IDESC_N256, 1);
            #pragma unroll
            for (int k = 0; k < 4; k++)
                mma_bf16_ss(tmem, al + 2 * k, bh + 2 * k, MMA_IDESC_N256, 1);
            TCGEN05_COMMIT(sb + SM_MB1);
        }
    }

    MBARRIER_WAIT_PARITY(sb + SM_MB0, 1);   // 4th completion on buf0 (chunks 0,2,4,6)
    MBARRIER_WAIT_PARITY(sb + SM_MB1, 1);   // 4th completion on buf1 (chunks 1,3,5,7)
    TCGEN05_FENCE_AFTER();

    if (wid < 4) {
        int m = wid * 32 + lid;
        int r = r0 + m;
        int b = r & (B - 1);
        const float4* gi4 = (const float4*)g_ginp;
        float* outp = g_gact + (size_t)r * G4 + n0;
        #pragma unroll
        for (int cb = 0; cb < 8; cb++) {
            uint32_t dr[32];
            TCGEN05_LD_32X32B_X32(dr, tmem + cb * 32);
            TCGEN05_WAIT_LD();
            #pragma unroll
            for (int q = 0; q < 8; q++) {
                float4 g = gi4[b * (G4 / 4) + (n0 >> 2) + cb * 8 + q];
                float4 v;
                v.x = __uint_as_float(dr[q * 4 + 0]) + g.x;
                v.y = __uint_as_float(dr[q * 4 + 1]) + g.y;
                v.z = __uint_as_float(dr[q * 4 + 2]) + g.z;
                v.w = __uint_as_float(dr[q * 4 + 3]) + g.w;
                *(float4*)(outp + cb * 32 + q * 4) = v;
            }
        }
        TCGEN05_FENCE_BEFORE();
    }
    __syncthreads();
    if (tid == 0) { MBARRIER_INVAL(sb + SM_MB0); MBARRIER_INVAL(sb + SM_MB1); }
    if (wid == 0) TCGEN05_DEALLOC(tmem, 256);
#else
    for (int o = 0; o < 128; o++) {
        int r = r0 + o;
        int n = n0 + tid;
        const float* ap = act + (size_t)r * ACT_F;
        const float* wp = W_ih + (size_t)n * LSTM_IN + IN_F;
        float acc = 0.0f;
        for (int k = 0; k < ACT_F; k++) acc += ap[k] * wp[k];
        g_gact[(size_t)r * G4 + n] = acc + g_ginp[(r & (B - 1)) * G4 + n];
    }
#endif
}

// ---------------- persistent decoder: all 128 steps in one kernel ----------------
// 32 CTAs (one wave), CTA owns j-slice [j0, j0+32). Global barrier between steps.
__global__ void __launch_bounds__(256, 1) decoder_kernel(const float* __restrict__ Whh,
                                                         float* __restrict__ out) {
    extern __shared__ char smem[];
    uint32_t sb = smem_u32(smem);
    const int tid = threadIdx.x;
    const int wid = tid >> 5;
    const int lid = tid & 31;
    const int j0 = blockIdx.x * 32;

#if HAS_TCGEN05
    if (wid == 0) TCGEN05_ALLOC(sb + SM_TMEM, 128);
    if (tid == 0) { MBARRIER_INIT(sb + SM_MB0, 1); MBARRIER_INIT(sb + SM_MB1, 1); }
    __syncthreads();
    uint32_t tmem;
    asm volatile("ld.shared.b32 %0, [%1];" : "=r"(tmem) : "r"(sb + SM_TMEM));
#endif

    for (int t = 0; t < L; t++) {
#if HAS_TCGEN05
        const char* whi = (const char*)g_Whh_hi;
        const char* wlo = (const char*)g_Whh_lo;
        const char* hhi = (const char*)g_h_hi[t & 1];
        const char* hlo = (const char*)g_h_lo[t & 1];

        for (int kc = 0; kc < 16; kc++) {
            const int buf = kc & 1;
            if (kc >= 2) {
                uint32_t mb = sb + (buf ? SM_MB1 : SM_MB0);
                MBARRIER_WAIT_PARITY(mb, ((kc >> 1) - 1) & 1);
            }
            uint32_t base = sb + SM_BUF + buf * BUF_STRIDE;
            #pragma unroll
            for (int i = 0; i < 4; i++) {
                int u = tid + i * 256;
                int row = u >> 3, q = u & 7;
                int wrow = ((row >> 5) << 10) + j0 + (row & 31);
                size_t so = ((size_t)wrow * 128 + kc * 8 + q) * 16;
                uint32_t d = base + OFF_AHI + swz(row * 128 + q * 16);
                CP_ASYNC16(d, whi + so);
                CP_ASYNC16(d + (OFF_ALO - OFF_AHI), wlo + so);
            }
            #pragma unroll
            for (int i = 0; i < 2; i++) {
                int u = tid + i * 256;
                int row = u >> 3, q = u & 7;
                size_t so = ((size_t)row * 128 + kc * 8 + q) * 16;
                uint32_t d = base + OFF_BHI + swz(row * 128 + q * 16);
                CP_ASYNC16(d, hhi + so);
                CP_ASYNC16(d + (OFF_BLO - OFF_BHI), hlo + so);
            }
            CP_COMMIT();
            if (kc >= 1) {
                CP_WAIT(1);
                __syncthreads();
                if (wid == 0) {
                    FENCE_PROXY_ASYNC_SHARED_CTA();
                    if (elect1()) {
                        int j = kc - 1;
                        uint32_t b2 = sb + SM_BUF + (j & 1) * BUF_STRIDE;
                        uint64_t ah = make_desc(b2 + OFF_AHI);
                        uint64_t al = make_desc(b2 + OFF_ALO);
                        uint64_t bh = make_desc(b2 + OFF_BHI);
                        uint64_t bl = make_desc(b2 + OFF_BLO);
                        #pragma unroll
                        for (int k = 0; k < 4; k++)
                            mma_bf16_ss(tmem, ah + 2 * k, bh + 2 * k, MMA_IDESC_N64, !(j == 0 && k == 0));
                        #pragma unroll
                        for (int k = 0; k < 4; k++)
                            mma_bf16_ss(tmem, ah + 2 * k, bl + 2 * k, MMA_IDESC_N64, 1);
                        #pragma unroll
                        for (int k = 0; k < 4; k++)
                            mma_bf16_ss(tmem, al + 2 * k, bh + 2 * k, MMA_IDESC_N64, 1);
                        TCGEN05_COMMIT(sb + ((j & 1) ? SM_MB1 : SM_MB0));
                    }
                }
            }
        }

        // stage gact slice via cp.async (overlaps chunk-15 landing + tail MMAs)
        {
            const char* gap = (const char*)(g_gact + (size_t)t * B * G4);
            #pragma unroll
            for (int i = 0; i < 8; i++) {
                int u = tid + i * 256;
                int b = u >> 5;
                int rem = u & 31;
                int g = rem >> 3, qq = rem & 7;
                size_t so = ((size_t)b * 4096 + g * 1024 + j0 + qq * 4) * 4;
                uint32_t d = sb + SM_GA + (b * 136 + g * 32 + qq * 4) * 4;
                CP_ASYNC16(d, gap + so);
            }
            CP_COMMIT();
        }
        CP_WAIT(0);
        __syncthreads();
        if (wid == 0) {
            FENCE_PROXY_ASYNC_SHARED_CTA();
            if (elect1()) {
                uint32_t b2 = sb + SM_BUF + BUF_STRIDE;   // buf1 (chunk 15)
                uint64_t ah = make_desc(b2 + OFF_AHI);
                uint64_t al = make_desc(b2 + OFF_ALO);
                uint64_t bh = make_desc(b2 + OFF_BHI);
                uint64_t bl = make_desc(b2 + OFF_BLO);
                #pragma unroll
                for (int k = 0; k < 4; k++)
                    mma_bf16_ss(tmem, ah + 2 * k, bh + 2 * k, MMA_IDESC_N64, 1);
                #pragma unroll
                for (int k = 0; k < 4; k++)
                    mma_bf16_ss(tmem, ah + 2 * k, bl + 2 * k, MMA_IDESC_N64, 1);
                #pragma unroll
                for (int k = 0; k < 4; k++)
                    mma_bf16_ss(tmem, al + 2 * k, bh + 2 * k, MMA_IDESC_N64, 1);
                TCGEN05_COMMIT(sb + SM_MB1);
            }
        }

        MBARRIER_WAIT_PARITY(sb + SM_MB0, 1);   // 8th completion this step (parity repeats every step)
        MBARRIER_WAIT_PARITY(sb + SM_MB1, 1);
        TCGEN05_FENCE_AFTER();

        // TMEM drain: 8 warps; warps 0-3 cols 0-31, warps 4-7 cols 32-63
        {
            int sp = wid & 3;                 // subpartition = rows [32sp, 32sp+32)
            int cb = (wid >> 2) * 32;         // column base
            uint32_t dr[32];
            TCGEN05_LD_32X32B_X32(dr, tmem + cb);
            TCGEN05_WAIT_LD();
            TCGEN05_FENCE_BEFORE();
            int r = sp * 32 + lid;
            float* sg = (float*)(smem + SM_G) + r * 68 + cb;
            #pragma unroll
            for (int c = 0; c < 32; c++) sg[c] = __uint_as_float(dr[c]);
        }
        __syncthreads();
#else
        // ---- SIMT fp32 fallback ----
        {
            float* sg = (float*)(smem + SM_G);
            float* hs = (float*)(smem + SM_BUF);
            const int r   = tid >> 1;
            const int bb0 = (tid & 1) * 32;
            const int wrow = ((r >> 5) << 10) + j0 + (r & 31);
            const float* wp = Whh + (size_t)wrow * H;
            float acc[32];
            #pragma unroll
            for (int i = 0; i < 32; i++) acc[i] = 0.0f;
            for (int kc = 0; kc < 8; kc++) {
                #pragma unroll
                for (int i = 0; i < 32; i++) {
                    int u = tid + i * 256;
                    int b = u >> 7, k = u & 127;
                    int gi = b * H + kc * 128 + k;
                    hs[b * 132 + k] = __bfloat162float(g_h_hi[t & 1][gi]) + __bfloat162float(g_h_lo[t & 1][gi]);
                }
                __syncthreads();
                for (int k = 0; k < 128; k++) {
                    float w = wp[kc * 128 + k];
                    #pragma unroll
                    for (int i = 0; i < 32; i++)
                        acc[i] += w * hs[(bb0 + i) * 132 + k];
                }
                __syncthreads();
            }
            #pragma unroll
            for (int i = 0; i < 32; i++) sg[r * 68 + bb0 + i] = acc[i];
        }
        {
            const float4* gap = (const float4*)(g_gact + (size_t)t * B * G4);
            float* sga = (float*)(smem + SM_GA);
            #pragma unroll
            for (int i = 0; i < 8; i++) {
                int u = tid + i * 256;
                int b = u >> 5;
                int rem = u & 31;
                int g = rem >> 3, qq = rem & 7;
                float4 v = gap[(size_t)b * 1024 + g * 256 + (j0 >> 2) + qq];
                *(float4*)(sga + b * 136 + g * 32 + qq * 4) = v;
            }
        }
        __syncthreads();
#endif

        // ---- LSTM cells: warp w handles batches [8w, 8w+8), lane = j ----
        {
            const float* sg  = (const float*)(smem + SM_G);
            const float* sga = (const float*)(smem + SM_GA);
            int b = wid * 8;
            #pragma unroll
            for (int k = 0; k < 8; k++, b++) {
                float s0 = sga[b * 136 +  0 + lid] + sg[( 0 + lid) * 68 + b];
                float s1 = sga[b * 136 + 32 + lid] + sg[(32 + lid) * 68 + b];
                float s2 = sga[b * 136 + 64 + lid] + sg[(64 + lid) * 68 + b];
                float s3 = sga[b * 136 + 96 + lid] + sg[(96 + lid) * 68 + b];
                int gidx = b * H + j0 + lid;
                float c = g_c[gidx];
                float i_ = sigm(s0);
                float f_ = sigm(s1);
                float gg = tanhf(s2);
                float o_ = sigm(s3);
                float cn = f_ * c + i_ * gg;
                float hn = o_ * tanhf(cn);
                g_c[gidx] = cn;
                out[(size_t)t * B * H + gidx] = hn;
                __nv_bfloat16 hb = __float2bfloat16(hn);
                g_h_hi[(t + 1) & 1][gidx] = hb;
                g_h_lo[(t + 1) & 1][gidx] = __float2bfloat16(hn - __bfloat162float(hb));
            }
        }

        // ---- global step barrier across 32 CTAs ----
        __threadfence();
        __syncthreads();
        if (tid == 0) {
            atomicAdd(&g_bar, 1u);
            unsigned target = 32u * (unsigned)(t + 1);
            unsigned v;
            do {
                asm volatile("ld.acquire.gpu.global.u32 %0, [%1];" : "=r"(v) : "l"(&g_bar));
            } while (v < target);
        }
        __syncthreads();
    }

#if HAS_TCGEN05
    if (tid == 0) { MBARRIER_INVAL(sb + SM_MB0); MBARRIER_INVAL(sb + SM_MB1); }
    if (wid == 0) TCGEN05_DEALLOC(tmem, 128);
#endif
}

// ---------------- tail: h_n, c_n ----------------
__global__ void tail_kernel(float* __restrict__ out) {
    int idx = blockIdx.x * blockDim.x + threadIdx.x;
    if (idx >= B * H) return;
    out[(size_t)L * B * H + idx]         = out[(size_t)(L - 1) * B * H + idx];
    out[(size_t)L * B * H + B * H + idx] = g_c[idx];
}

extern "C" void kernel_launch(void* const* d_in, const int* in_sizes, int n_in,
                              void* d_out, int out_size) {
    const float* inp  = (const float*)d_in[0];
    const float* act  = (const float*)d_in[1];
    const float* h0   = (const float*)d_in[2];
    const float* c0   = (const float*)d_in[3];
    const float* W_ih = (const float*)d_in[4];
    const float* W_hh = (const float*)d_in[5];
    const float* b_ih = (const float*)d_in[6];
    const float* b_hh = (const float*)d_in[7];
    float* out = (float*)d_out;
    (void)in_sizes; (void)n_in;

    cudaFuncSetAttribute(decoder_kernel, cudaFuncAttributeMaxDynamicSharedMemorySize, SMEM_TOTAL);
    cudaFuncSetAttribute(gact_tc_kernel, cudaFuncAttributeMaxDynamicSharedMemorySize, GT_SMEM_TOTAL);

    init_state_kernel<<<(B * H + 255) / 256, 256>>>(h0, c0);
    wsplit_kernel<<<(G4 * H + 255) / 256, 256>>>(W_hh);
    asplit_kernel<<<(L * B * ACT_F + 255) / 256, 256>>>(act);
    wisplit_kernel<<<(G4 * ACT_F + 255) / 256, 256>>>(W_ih);
    ginp_kernel<<<32, 256>>>(inp, W_ih, b_ih, b_hh);
    gact_tc_kernel<<<dim3(16, 64), 256, GT_SMEM_TOTAL>>>(act, W_ih);

    decoder_kernel<<<32, 256, SMEM_TOTAL>>>(W_hh, out);

    if (out_size >= L * B * H + 2 * B * H) {
        tail_kernel<<<(B * H + 255) / 256, 256>>>(out);
    }
}

// round 6
// speedup vs baseline: 2.2076x; 1.1296x over previous
#include <cuda_runtime.h>
#include <cuda_bf16.h>
#include <stdint.h>
#include <math.h>

#define L      128
#define B      64
#define IN_F   512
#define ACT_F  512
#define H      1024
#define G4     4096
#define LSTM_IN 1024

#if defined(__CUDA_ARCH__) && (defined(__CUDA_ARCH_FEAT_SM103_ALL) || defined(__CUDA_ARCH_FEAT_SM100_ALL) || defined(__CUDA_ARCH_SPECIFIC__) || defined(__CUDA_ARCH_FAMILY_SPECIFIC__))
#define HAS_TCGEN05 1
#else
#define HAS_TCGEN05 0
#endif

// ---------------- device scratch ----------------
__device__ float g_gact[(size_t)L * B * G4];
__device__ float g_ginp[B * G4];
__device__ float g_c[B * H];
__device__ __nv_bfloat16 g_Whh_hi[G4 * H];
__device__ __nv_bfloat16 g_Whh_lo[G4 * H];
__device__ __nv_bfloat16 g_h_hi[2][B * H];
__device__ __nv_bfloat16 g_h_lo[2][B * H];
__device__ __nv_bfloat16 g_act_hi[(size_t)L * B * ACT_F];
__device__ __nv_bfloat16 g_act_lo[(size_t)L * B * ACT_F];
__device__ __nv_bfloat16 g_Wact_hi[G4 * ACT_F];
__device__ __nv_bfloat16 g_Wact_lo[G4 * ACT_F];
__device__ unsigned g_bar;

__device__ __forceinline__ float sigm_fast(float x) {
    return __fdividef(1.0f, 1.0f + __expf(-x));
}
__device__ __forceinline__ float tanh_fast(float x) {
    return 1.0f - __fdividef(2.0f, __expf(2.0f * x) + 1.0f);
}
__device__ __forceinline__ float sigm(float x) { return 1.0f / (1.0f + expf(-x)); }

// ---------------- PTX helpers ----------------
__device__ __forceinline__ uint32_t smem_u32(const void* p) {
    uint32_t a;
    asm("{ .reg .u64 t; cvta.to.shared.u64 t, %1; cvt.u32.u64 %0, t; }" : "=r"(a) : "l"(p));
    return a;
}

#define CP_ASYNC16(dst, src) \
    asm volatile("cp.async.cg.shared.global [%0], [%1], 16;" :: "r"((uint32_t)(dst)), "l"(src) : "memory")
#define CP_COMMIT() asm volatile("cp.async.commit_group;" ::: "memory")
#define CP_WAIT(n)  asm volatile("cp.async.wait_group %0;" :: "n"(n) : "memory")

#define MBARRIER_INIT(addr, cnt) \
    asm volatile("mbarrier.init.shared.b64 [%0], %1;" :: "r"((uint32_t)(addr)), "r"((uint32_t)(cnt)) : "memory")
#define MBARRIER_INVAL(addr) \
    asm volatile("mbarrier.inval.shared.b64 [%0];" :: "r"((uint32_t)(addr)) : "memory")

#define MBARRIER_WAIT_PARITY(mbar_smem_addr, phase_parity) do { \
    uint32_t _mbar = (uint32_t)(mbar_smem_addr); \
    uint32_t _parity = (uint32_t)(phase_parity); \
    uint32_t _done; \
    asm volatile( \
        "{\n\t" \
        ".reg .pred p;\n\t" \
        "mbarrier.try_wait.parity.acquire.cta.shared::cta.b64 p, [%1], %2;\n\t" \
        "selp.b32 %0, 1, 0, p;\n\t" \
        "}" \
        : "=r"(_done) : "r"(_mbar), "r"(_parity) : "memory"); \
    if (!_done) { \
        asm volatile( \
            "{\n\t" \
            ".reg .pred P1;\n\t" \
            "WAIT_LOOP_%=:\n\t" \
            "mbarrier.try_wait.parity.acquire.cta.shared::cta.b64 P1, [%0], %1, 0x989680;\n\t" \
            "@P1 bra.uni WAIT_DONE_%=;\n\t" \
            "bra.uni WAIT_LOOP_%=;\n\t" \
            "WAIT_DONE_%=:\n\t" \
            "}" \
            :: "r"(_mbar), "r"(_parity) : "memory"); \
    } \
} while(0)

#if HAS_TCGEN05
__device__ __forceinline__ uint32_t elect1() {
    uint32_t p;
    asm volatile("{ .reg .pred p; elect.sync _|p, 0xFFFFFFFF; selp.b32 %0, 1, 0, p; }" : "=r"(p));
    return p;
}

#define TCGEN05_ALLOC(smem_result_addr, nCols) \
    asm volatile("tcgen05.alloc.cta_group::1.sync.aligned.shared::cta.b32 [%0], %1;" \
        :: "r"((uint32_t)(smem_result_addr)), "r"((uint32_t)(nCols)) : "memory")
#define TCGEN05_DEALLOC(tmem_addr, nCols) \
    asm volatile("tcgen05.dealloc.cta_group::1.sync.aligned.b32 %0, %1;" :: "r"(tmem_addr), "r"(nCols))
#define TCGEN05_COMMIT(mbar_smem_addr) \
    asm volatile("tcgen05.commit.cta_group::1.mbarrier::arrive::one.shared::cluster.b64 [%0];" \
        :: "r"((uint32_t)(mbar_smem_addr)) : "memory")
#define TCGEN05_FENCE_AFTER() asm volatile("tcgen05.fence::after_thread_sync;" ::: "memory")
#define TCGEN05_FENCE_BEFORE() asm volatile("tcgen05.fence::before_thread_sync;" ::: "memory")
#define TCGEN05_WAIT_LD() asm volatile("tcgen05.wait::ld.sync.aligned;" ::: "memory")
#define FENCE_PROXY_ASYNC_SHARED_CTA() asm volatile("fence.proxy.async.shared::cta;" ::: "memory")

#define TCGEN05_LD_32X32B_X32(r, tmem_addr) \
    asm volatile( \
        "tcgen05.ld.sync.aligned.32x32b.x32.b32 " \
        "{%0, %1, %2, %3, %4, %5, %6, %7, " \
        " %8, %9, %10, %11, %12, %13, %14, %15, " \
        " %16, %17, %18, %19, %20, %21, %22, %23, " \
        " %24, %25, %26, %27, %28, %29, %30, %31}, [%32];" \
        : "=r"((r)[0]),  "=r"((r)[1]),  "=r"((r)[2]),  "=r"((r)[3]), \
          "=r"((r)[4]),  "=r"((r)[5]),  "=r"((r)[6]),  "=r"((r)[7]), \
          "=r"((r)[8]),  "=r"((r)[9]),  "=r"((r)[10]), "=r"((r)[11]), \
          "=r"((r)[12]), "=r"((r)[13]), "=r"((r)[14]), "=r"((r)[15]), \
          "=r"((r)[16]), "=r"((r)[17]), "=r"((r)[18]), "=r"((r)[19]), \
          "=r"((r)[20]), "=r"((r)[21]), "=r"((r)[22]), "=r"((r)[23]), \
          "=r"((r)[24]), "=r"((r)[25]), "=r"((r)[26]), "=r"((r)[27]), \
          "=r"((r)[28]), "=r"((r)[29]), "=r"((r)[30]), "=r"((r)[31]) \
        : "r"(tmem_addr))

__device__ __forceinline__ void mma_bf16_ss(uint32_t d, uint64_t a, uint64_t b,
                                            uint32_t idesc, uint32_t en) {
    asm volatile(
        "{\n\t"
        ".reg .pred p;\n\t"
        "setp.ne.u32 p, %5, 0;\n\t"
        "tcgen05.mma.cta_group::1.kind::f16 [%0], %1, %2, %3, {%4, %4, %4, %4}, p;\n\t"
        "}"
        :: "r"(d), "l"(a), "l"(b), "r"(idesc), "r"(0u), "r"(en) : "memory");
}

static __device__ __forceinline__ uint64_t make_desc(uint32_t base) {
    const uint64_t BASE =
        (uint64_t(2) << 61) | (uint64_t(1) << 46) | (uint64_t(64) << 32) | (uint64_t(1) << 16);
    return BASE | ((uint64_t)(base >> 4) & 0x3FFF);
}
#endif // HAS_TCGEN05

__device__ __forceinline__ uint32_t swz(uint32_t x) { return x ^ ((x >> 3) & 0x70); }

#define MMA_IDESC_N64  0x8100490u
#define MMA_IDESC_N256 0x8400490u

// ---------------- SMEM layout: persistent decoder (3-stage ring) ----------------
#define SM_TMEM   0
#define SM_MB0    8
#define SM_MB1    16
#define SM_MB2    24
#define SM_BUF    1024
#define BUF_STRIDE 49152
#define OFF_AHI   0
#define OFF_ALO   16384
#define OFF_BHI   32768
#define OFF_BLO   40960
#define SM_G      (1024 + 3 * BUF_STRIDE)       // 148480
#define SM_GA     (SM_G + 34816)                // 183296
#define SMEM_TOTAL (SM_GA + 34816)              // 218112

// ---------------- SMEM layout: gact_tc kernel ----------------
#define GT_STRIDE 98304
#define GT_AHI    0
#define GT_ALO    16384
#define GT_BHI    32768
#define GT_BLO    65536
#define GT_SMEM_TOTAL (1024 + 2 * GT_STRIDE)

// ---------------- init ----------------
__global__ void init_state_kernel(const float* __restrict__ h0, const float* __restrict__ c0) {
    int i = blockIdx.x * blockDim.x + threadIdx.x;
    if (i == 0) g_bar = 0;
    if (i < B * H) {
        g_c[i] = c0[i];
        float h = h0[i];
        __nv_bfloat16 hi = __float2bfloat16(h);
        g_h_hi[0][i] = hi;
        g_h_lo[0][i] = __float2bfloat16(h - __bfloat162float(hi));
    }
}

__global__ void wsplit_kernel(const float* __restrict__ W) {
    int i = blockIdx.x * blockDim.x + threadIdx.x;
    if (i < G4 * H) {
        float w = W[i];
        __nv_bfloat16 hi = __float2bfloat16(w);
        g_Whh_hi[i] = hi;
        g_Whh_lo[i] = __float2bfloat16(w - __bfloat162float(hi));
    }
}

__global__ void asplit_kernel(const float* __restrict__ act) {
    int i = blockIdx.x * blockDim.x + threadIdx.x;
    if (i < L * B * ACT_F) {
        float v = act[i];
        __nv_bfloat16 hi = __float2bfloat16(v);
        g_act_hi[i] = hi;
        g_act_lo[i] = __float2bfloat16(v - __bfloat162float(hi));
    }
}

__global__ void wisplit_kernel(const float* __restrict__ W_ih) {
    int i = blockIdx.x * blockDim.x + threadIdx.x;
    if (i < G4 * ACT_F) {
        int n = i >> 9, k = i & 511;
        float w = W_ih[(size_t)n * LSTM_IN + IN_F + k];
        __nv_bfloat16 hi = __float2bfloat16(w);
        g_Wact_hi[i] = hi;
        g_Wact_lo[i] = __float2bfloat16(w - __bfloat162float(hi));
    }
}

// ---------------- ginp (fp32) ----------------
__global__ void ginp_kernel(const float* __restrict__ inp,
                            const float* __restrict__ W_ih,
                            const float* __restrict__ b_ih,
                            const float* __restrict__ b_hh) {
    __shared__ float aT[16][68];
    __shared__ float wT[16][132];
    const int nb0 = blockIdx.x * 128;
    const int tid = threadIdx.x;
    const int tx = tid & 31;
    const int ty = tid >> 5;
    float acc[8][4];
    #pragma unroll
    for (int i = 0; i < 8; i++)
        #pragma unroll
        for (int j = 0; j < 4; j++) acc[i][j] = 0.0f;

    const int lb  = tid >> 2;
    const int lq  = (tid & 3) * 4;
    const int lc  = tid >> 1;
    const int lhf = (tid & 1) * 8;

    for (int k0 = 0; k0 < IN_F; k0 += 16) {
        {
            float4 v = *(const float4*)(inp + lb * IN_F + k0 + lq);
            aT[lq + 0][lb] = v.x; aT[lq + 1][lb] = v.y;
            aT[lq + 2][lb] = v.z; aT[lq + 3][lb] = v.w;
        }
        {
            const float* wp = W_ih + (size_t)(nb0 + lc) * LSTM_IN + k0 + lhf;
            float4 v0 = *(const float4*)(wp);
            float4 v1 = *(const float4*)(wp + 4);
            wT[lhf + 0][lc] = v0.x; wT[lhf + 1][lc] = v0.y;
            wT[lhf + 2][lc] = v0.z; wT[lhf + 3][lc] = v0.w;
            wT[lhf + 4][lc] = v1.x; wT[lhf + 5][lc] = v1.y;
            wT[lhf + 6][lc] = v1.z; wT[lhf + 7][lc] = v1.w;
        }
        __syncthreads();
        #pragma unroll
        for (int kk = 0; kk < 16; kk++) {
            float av[8];
            float4 u0 = *(const float4*)&aT[kk][ty * 8];
            float4 u1 = *(const float4*)&aT[kk][ty * 8 + 4];
            av[0] = u0.x; av[1] = u0.y; av[2] = u0.z; av[3] = u0.w;
            av[4] = u1.x; av[5] = u1.y; av[6] = u1.z; av[7] = u1.w;
            float wv[4];
            #pragma unroll
            for (int jj = 0; jj < 4; jj++) wv[jj] = wT[kk][tx + 32 * jj];
            #pragma unroll
            for (int i = 0; i < 8; i++)
                #pragma unroll
                for (int jj = 0; jj < 4; jj++) acc[i][jj] += av[i] * wv[jj];
        }
        __syncthreads();
    }
    #pragma unroll
    for (int jj = 0; jj < 4; jj++) {
        int n = nb0 + tx + 32 * jj;
        float bb = b_ih[n] + b_hh[n];
        #pragma unroll
        for (int i = 0; i < 8; i++) {
            int b = ty * 8 + i;
            g_ginp[b * G4 + n] = acc[i][jj] + bb;
        }
    }
}

// ---------------- gact_tc ----------------
__global__ void __launch_bounds__(256, 1) gact_tc_kernel(const float* __restrict__ act,
                                                         const float* __restrict__ W_ih) {
    extern __shared__ char smem[];
    const int tid = threadIdx.x;
    const int n0 = blockIdx.x * 256;
    const int r0 = blockIdx.y * 128;

#if HAS_TCGEN05
    uint32_t sb = smem_u32(smem);
    const int wid = tid >> 5;
    const int lid = tid & 31;

    if (wid == 0) TCGEN05_ALLOC(sb + SM_TMEM, 256);
    if (tid == 0) { MBARRIER_INIT(sb + SM_MB0, 1); MBARRIER_INIT(sb + SM_MB1, 1); }
    __syncthreads();
    uint32_t tmem;
    asm volatile("ld.shared.b32 %0, [%1];" : "=r"(tmem) : "r"(sb + SM_TMEM));

    const char* ahi = (const char*)g_act_hi;
    const char* alo = (const char*)g_act_lo;
    const char* whi = (const char*)g_Wact_hi;
    const char* wlo = (const char*)g_Wact_lo;

    for (int kc = 0; kc < 8; kc++) {
        const int buf = kc & 1;
        if (kc >= 2) {
            uint32_t mb = sb + (buf ? SM_MB1 : SM_MB0);
            MBARRIER_WAIT_PARITY(mb, ((kc >> 1) - 1) & 1);
        }
        uint32_t base = sb + 1024 + buf * GT_STRIDE;
        #pragma unroll
        for (int i = 0; i < 4; i++) {
            int u = tid + i * 256;
            int row = u >> 3, q = u & 7;
            size_t so = ((size_t)(r0 + row) * 64 + kc * 8 + q) * 16;
            uint32_t d = base + GT_AHI + swz(row * 128 + q * 16);
            CP_ASYNC16(d, ahi + so);
            CP_ASYNC16(d + (GT_ALO - GT_AHI), alo + so);
        }
        #pragma unroll
        for (int i = 0; i < 8; i++) {
            int u = tid + i * 256;
            int row = u >> 3, q = u & 7;
            size_t so = ((size_t)(n0 + row) * 64 + kc * 8 + q) * 16;
            uint32_t d = base + GT_BHI + swz(row * 128 + q * 16);
            CP_ASYNC16(d, whi + so);
            CP_ASYNC16(d + (GT_BLO - GT_BHI), wlo + so);
        }
        CP_COMMIT();
        if (kc >= 1) {
            CP_WAIT(1);
            __syncthreads();
            if (wid == 0) {
                FENCE_PROXY_ASYNC_SHARED_CTA();
                if (elect1()) {
                    int j = kc - 1;
                    uint32_t b2 = sb + 1024 + (j & 1) * GT_STRIDE;
                    uint64_t ah = make_desc(b2 + GT_AHI);
                    uint64_t al = make_desc(b2 + GT_ALO);
                    uint64_t bh = make_desc(b2 + GT_BHI);
                    uint64_t bl = make_desc(b2 + GT_BLO);
                    #pragma unroll
                    for (int k = 0; k < 4; k++)
                        mma_bf16_ss(tmem, ah + 2 * k, bh + 2 * k, MMA_IDESC_N256, !(j == 0 && k == 0));
                    #pragma unroll
                    for (int k = 0; k < 4; k++)
                        mma_bf16_ss(tmem, ah + 2 * k, bl + 2 * k, MMA_IDESC_N256, 1);
                    #pragma unroll
                    for (int k = 0; k < 4; k++)
                        mma_bf16_ss(tmem, al + 2 * k, bh + 2 * k, MMA_IDESC_N256, 1);
                    TCGEN05_COMMIT(sb + ((j & 1) ? SM_MB1 : SM_MB0));
                }
            }
        }
    }
    CP_WAIT(0);
    __syncthreads();
    if (wid == 0) {
        FENCE_PROXY_ASYNC_SHARED_CTA();
        if (elect1()) {
            uint32_t b2 = sb + 1024 + GT_STRIDE;
            uint64_t ah = make_desc(b2 + GT_AHI);
            uint64_t al = make_desc(b2 + GT_ALO);
            uint64_t bh = make_desc(b2 + GT_BHI);
            uint64_t bl = make_desc(b2 + GT_BLO);
            #pragma unroll
            for (int k = 0; k < 4; k++)
                mma_bf16_ss(tmem, ah + 2 * k, bh + 2 * k, MMA_IDESC_N256, 1);
            #pragma unroll
            for (int k = 0; k < 4; k++)
                mma_bf16_ss(tmem, ah + 2 * k, bl + 2 * k, MMA_IDESC_N256, 1);
            #pragma unroll
            for (int k = 0; k < 4; k++)
                mma_bf16_ss(tmem, al + 2 * k, bh + 2 * k, MMA_IDESC_N256, 1);
            TCGEN05_COMMIT(sb + SM_MB1);
        }
    }

    MBARRIER_WAIT_PARITY(sb + SM_MB0, 1);
    MBARRIER_WAIT_PARITY(sb + SM_MB1, 1);
    TCGEN05_FENCE_AFTER();

    if (wid < 4) {
        int m = wid * 32 + lid;
        int r = r0 + m;
        int b = r & (B - 1);
        const float4* gi4 = (const float4*)g_ginp;
        float* outp = g_gact + (size_t)r * G4 + n0;
        #pragma unroll
        for (int cb = 0; cb < 8; cb++) {
            uint32_t dr[32];
            TCGEN05_LD_32X32B_X32(dr, tmem + cb * 32);
            TCGEN05_WAIT_LD();
            #pragma unroll
            for (int q = 0; q < 8; q++) {
                float4 g = gi4[b * (G4 / 4) + (n0 >> 2) + cb * 8 + q];
                float4 v;
                v.x = __uint_as_float(dr[q * 4 + 0]) + g.x;
                v.y = __uint_as_float(dr[q * 4 + 1]) + g.y;
                v.z = __uint_as_float(dr[q * 4 + 2]) + g.z;
                v.w = __uint_as_float(dr[q * 4 + 3]) + g.w;
                *(float4*)(outp + cb * 32 + q * 4) = v;
            }
        }
        TCGEN05_FENCE_BEFORE();
    }
    __syncthreads();
    if (tid == 0) { MBARRIER_INVAL(sb + SM_MB0); MBARRIER_INVAL(sb + SM_MB1); }
    if (wid == 0) TCGEN05_DEALLOC(tmem, 256);
#else
    for (int o = 0; o < 128; o++) {
        int r = r0 + o;
        int n = n0 + tid;
        const float* ap = act + (size_t)r * ACT_F;
        const float* wp = W_ih + (size_t)n * LSTM_IN + IN_F;
        float acc = 0.0f;
        for (int k = 0; k < ACT_F; k++) acc += ap[k] * wp[k];
        g_gact[(size_t)r * G4 + n] = acc + g_ginp[(r & (B - 1)) * G4 + n];
    }
#endif
}

#if HAS_TCGEN05
// ---------------- decoder helpers ----------------
__device__ __forceinline__ void issue_W(uint32_t base, int n, int tid, int j0,
                                        const char* whi, const char* wlo) {
    #pragma unroll
    for (int i = 0; i < 4; i++) {
        int u = tid + i * 256;
        int row = u >> 3, q = u & 7;
        int wrow = ((row >> 5) << 10) + j0 + (row & 31);
        size_t so = ((size_t)wrow * 128 + n * 8 + q) * 16;
        uint32_t d = base + OFF_AHI + swz(row * 128 + q * 16);
        CP_ASYNC16(d, whi + so);
        CP_ASYNC16(d + (OFF_ALO - OFF_AHI), wlo + so);
    }
}
__device__ __forceinline__ void issue_h(uint32_t base, int n, int tid,
                                        const char* hhi, const char* hlo) {
    #pragma unroll
    for (int i = 0; i < 2; i++) {
        int u = tid + i * 256;
        int row = u >> 3, q = u & 7;
        size_t so = ((size_t)row * 128 + n * 8 + q) * 16;
        uint32_t d = base + OFF_BHI + swz(row * 128 + q * 16);
        CP_ASYNC16(d, hhi + so);
        CP_ASYNC16(d + (OFF_BLO - OFF_BHI), hlo + so);
    }
}
__device__ __forceinline__ void issue_GA(uint32_t sb, int t, int tid, int j0) {
    const char* gap = (const char*)(g_gact + (size_t)t * B * G4);
    #pragma unroll
    for (int i = 0; i < 8; i++) {
        int u = tid + i * 256;
        int b = u >> 5;
        int rem = u & 31;
        int g = rem >> 3, qq = rem & 7;
        size_t so = ((size_t)b * 4096 + g * 1024 + j0 + qq * 4) * 4;
        uint32_t d = sb + SM_GA + (b * 136 + g * 32 + qq * 4) * 4;
        CP_ASYNC16(d, gap + so);
    }
    CP_COMMIT();
}
__device__ __forceinline__ void issue_mma(uint32_t tmem, uint32_t base, uint32_t mbar, int first) {
    uint64_t ah = make_desc(base + OFF_AHI);
    uint64_t al = make_desc(base + OFF_ALO);
    uint64_t bh = make_desc(base + OFF_BHI);
    uint64_t bl = make_desc(base + OFF_BLO);
    #pragma unroll
    for (int k = 0; k < 4; k++)
        mma_bf16_ss(tmem, ah + 2 * k, bh + 2 * k, MMA_IDESC_N64, !(first && k == 0));
    #pragma unroll
    for (int k = 0; k < 4; k++)
        mma_bf16_ss(tmem, ah + 2 * k, bl + 2 * k, MMA_IDESC_N64, 1);
    #pragma unroll
    for (int k = 0; k < 4; k++)
        mma_bf16_ss(tmem, al + 2 * k, bh + 2 * k, MMA_IDESC_N64, 1);
    TCGEN05_COMMIT(mbar);
}
#endif

// ---------------- persistent decoder ----------------
__global__ void __launch_bounds__(256, 1) decoder_kernel(const float* __restrict__ Whh,
                                                         float* __restrict__ out) {
    extern __shared__ char smem[];
    uint32_t sb = smem_u32(smem);
    const int tid = threadIdx.x;
    const int wid = tid >> 5;
    const int lid = tid & 31;
    const int j0 = blockIdx.x * 32;

#if HAS_TCGEN05
    if (wid == 0) TCGEN05_ALLOC(sb + SM_TMEM, 128);
    if (tid == 0) { MBARRIER_INIT(sb + SM_MB0, 1); MBARRIER_INIT(sb + SM_MB1, 1); MBARRIER_INIT(sb + SM_MB2, 1); }
    __syncthreads();
    uint32_t tmem;
    asm volatile("ld.shared.b32 %0, [%1];" : "=r"(tmem) : "r"(sb + SM_TMEM));

    const char* whi = (const char*)g_Whh_hi;
    const char* wlo = (const char*)g_Whh_lo;
    uint32_t wc[3] = {0, 0, 0};     // per-buffer mbarrier wait counters

    // prologue for step 0: W chunks 0,1 + gact slice (no h dependency)
    issue_W(sb + SM_BUF, 0, tid, j0, whi, wlo); CP_COMMIT();
    issue_W(sb + SM_BUF + BUF_STRIDE, 1, tid, j0, whi, wlo); CP_COMMIT();
    issue_GA(sb, 0, tid, j0);
#endif

    for (int t = 0; t < L; t++) {
#if HAS_TCGEN05
        const char* hhi = (const char*)g_h_hi[t & 1];
        const char* hlo = (const char*)g_h_lo[t & 1];

        // h for chunks 0, 1 (post-barrier: h is valid)
        issue_h(sb + SM_BUF, 0, tid, hhi, hlo); CP_COMMIT();
        issue_h(sb + SM_BUF + BUF_STRIDE, 1, tid, hhi, hlo); CP_COMMIT();

        #pragma unroll
        for (int kc = 0; kc < 16; kc++) {
            const int n = kc + 2;
            if (n <= 15) {
                const int b = n % 3;
                if (n >= 3) {
                    // buffer b last used by chunk n-3 = kc-1; wait its MMA completion
                    MBARRIER_WAIT_PARITY(sb + SM_MB0 + 8 * b, wc[b] & 1);
                    wc[b]++;
                }
                uint32_t base = sb + SM_BUF + b * BUF_STRIDE;
                issue_W(base, n, tid, j0, whi, wlo);
                issue_h(base, n, tid, hhi, hlo);
                CP_COMMIT();
            }
            if (kc < 14) { CP_WAIT(2); } else if (kc == 14) { CP_WAIT(1); } else { CP_WAIT(0); }
            __syncthreads();
            if (wid == 0) {
                FENCE_PROXY_ASYNC_SHARED_CTA();
                if (elect1()) {
                    const int b = kc % 3;
                    issue_mma(tmem, sb + SM_BUF + b * BUF_STRIDE, sb + SM_MB0 + 8 * b, kc == 0);
                }
            }
        }

        // wait remaining completions: chunk 13 (buf1), 14 (buf2), 15 (buf0)
        MBARRIER_WAIT_PARITY(sb + SM_MB1, wc[1] & 1); wc[1]++;
        MBARRIER_WAIT_PARITY(sb + SM_MB2, wc[2] & 1); wc[2]++;
        MBARRIER_WAIT_PARITY(sb + SM_MB0, wc[0] & 1); wc[0]++;
        TCGEN05_FENCE_AFTER();

        // prologue W for next step (buffers now free; overlaps drain/epilogue/barrier)
        if (t < L - 1) {
            issue_W(sb + SM_BUF, 0, tid, j0, whi, wlo); CP_COMMIT();
            issue_W(sb + SM_BUF + BUF_STRIDE, 1, tid, j0, whi, wlo); CP_COMMIT();
        }

        // TMEM drain: 8 warps
        {
            int sp = wid & 3;
            int cb = (wid >> 2) * 32;
            uint32_t dr[32];
            TCGEN05_LD_32X32B_X32(dr, tmem + cb);
            TCGEN05_WAIT_LD();
            TCGEN05_FENCE_BEFORE();
            int r = sp * 32 + lid;
            float* sg = (float*)(smem + SM_G) + r * 68 + cb;
            #pragma unroll
            for (int c = 0; c < 32; c++) sg[c] = __uint_as_float(dr[c]);
        }
        __syncthreads();
#else
        {
            float* sg = (float*)(smem + SM_G);
            float* hs = (float*)(smem + SM_BUF);
            const int r   = tid >> 1;
            const int bb0 = (tid & 1) * 32;
            const int wrow = ((r >> 5) << 10) + j0 + (r & 31);
            const float* wp = Whh + (size_t)wrow * H;
            float acc[32];
            #pragma unroll
            for (int i = 0; i < 32; i++) acc[i] = 0.0f;
            for (int kc = 0; kc < 8; kc++) {
                #pragma unroll
                for (int i = 0; i < 32; i++) {
                    int u = tid + i * 256;
                    int b = u >> 7, k = u & 127;
                    int gi = b * H + kc * 128 + k;
                    hs[b * 132 + k] = __bfloat162float(g_h_hi[t & 1][gi]) + __bfloat162float(g_h_lo[t & 1][gi]);
                }
                __syncthreads();
                for (int k = 0; k < 128; k++) {
                    float w = wp[kc * 128 + k];
                    #pragma unroll
                    for (int i = 0; i < 32; i++)
                        acc[i] += w * hs[(bb0 + i) * 132 + k];
                }
                __syncthreads();
            }
            #pragma unroll
            for (int i = 0; i < 32; i++) sg[r * 68 + bb0 + i] = acc[i];
        }
        {
            const float4* gap = (const float4*)(g_gact + (size_t)t * B * G4);
            float* sga = (float*)(smem + SM_GA);
            #pragma unroll
            for (int i = 0; i < 8; i++) {
                int u = tid + i * 256;
                int b = u >> 5;
                int rem = u & 31;
                int g = rem >> 3, qq = rem & 7;
                float4 v = gap[(size_t)b * 1024 + g * 256 + (j0 >> 2) + qq];
                *(float4*)(sga + b * 136 + g * 32 + qq * 4) = v;
            }
        }
        __syncthreads();
#endif

        // ---- LSTM cells (fast transcendental path) ----
        {
            const float* sg  = (const float*)(smem + SM_G);
            const float* sga = (const float*)(smem + SM_GA);
            int b = wid * 8;
            #pragma unroll
            for (int k = 0; k < 8; k++, b++) {
                float s0 = sga[b * 136 +  0 + lid] + sg[( 0 + lid) * 68 + b];
                float s1 = sga[b * 136 + 32 + lid] + sg[(32 + lid) * 68 + b];
                float s2 = sga[b * 136 + 64 + lid] + sg[(64 + lid) * 68 + b];
                float s3 = sga[b * 136 + 96 + lid] + sg[(96 + lid) * 68 + b];
                int gidx = b * H + j0 + lid;
                float c = g_c[gidx];
                float i_ = sigm_fast(s0);
                float f_ = sigm_fast(s1);
                float gg = tanh_fast(s2);
                float o_ = sigm_fast(s3);
                float cn = f_ * c + i_ * gg;
                float hn = o_ * tanh_fast(cn);
                g_c[gidx] = cn;
                out[(size_t)t * B * H + gidx] = hn;
                __nv_bfloat16 hb = __float2bfloat16(hn);
                g_h_hi[(t + 1) & 1][gidx] = hb;
                g_h_lo[(t + 1) & 1][gidx] = __float2bfloat16(hn - __bfloat162float(hb));
            }
        }

        // ---- global step barrier ----
        __threadfence();
        __syncthreads();
#if HAS_TCGEN05
        if (t < L - 1) issue_GA(sb, t + 1, tid, j0);   // prefetch next gact slice over barrier
#endif
        if (tid == 0) {
            atomicAdd(&g_bar, 1u);
            unsigned target = 32u * (unsigned)(t + 1);
            unsigned v;
            do {
                asm volatile("ld.acquire.gpu.global.u32 %0, [%1];" : "=r"(v) : "l"(&g_bar));
            } while (v < target);
        }
        __syncthreads();
    }

#if HAS_TCGEN05
    if (tid == 0) { MBARRIER_INVAL(sb + SM_MB0); MBARRIER_INVAL(sb + SM_MB1); MBARRIER_INVAL(sb + SM_MB2); }
    if (wid == 0) TCGEN05_DEALLOC(tmem, 128);
#endif
}

// ---------------- tail ----------------
__global__ void tail_kernel(float* __restrict__ out) {
    int idx = blockIdx.x * blockDim.x + threadIdx.x;
    if (idx >= B * H) return;
    out[(size_t)L * B * H + idx]         = out[(size_t)(L - 1) * B * H + idx];
    out[(size_t)L * B * H + B * H + idx] = g_c[idx];
}

extern "C" void kernel_launch(void* const* d_in, const int* in_sizes, int n_in,
                              void* d_out, int out_size) {
    const float* inp  = (const float*)d_in[0];
    const float* act  = (const float*)d_in[1];
    const float* h0   = (const float*)d_in[2];
    const float* c0   = (const float*)d_in[3];
    const float* W_ih = (const float*)d_in[4];
    const float* W_hh = (const float*)d_in[5];
    const float* b_ih = (const float*)d_in[6];
    const float* b_hh = (const float*)d_in[7];
    float* out = (float*)d_out;
    (void)in_sizes; (void)n_in;

    cudaFuncSetAttribute(decoder_kernel, cudaFuncAttributeMaxDynamicSharedMemorySize, SMEM_TOTAL);
    cudaFuncSetAttribute(gact_tc_kernel, cudaFuncAttributeMaxDynamicSharedMemorySize, GT_SMEM_TOTAL);

    init_state_kernel<<<(B * H + 255) / 256, 256>>>(h0, c0);
    wsplit_kernel<<<(G4 * H + 255) / 256, 256>>>(W_hh);
    asplit_kernel<<<(L * B * ACT_F + 255) / 256, 256>>>(act);
    wisplit_kernel<<<(G4 * ACT_F + 255) / 256, 256>>>(W_ih);
    ginp_kernel<<<32, 256>>>(inp, W_ih, b_ih, b_hh);
    gact_tc_kernel<<<dim3(16, 64), 256, GT_SMEM_TOTAL>>>(act, W_ih);

    decoder_kernel<<<32, 256, SMEM_TOTAL>>>(W_hh, out);

    if (out_size >= L * B * H + 2 * B * H) {
        tail_kernel<<<(B * H + 255) / 256, 256>>>(out);
    }
}

// round 7
// speedup vs baseline: 2.2192x; 1.0052x over previous
#include <cuda_runtime.h>
#include <cuda_bf16.h>
#include <stdint.h>
#include <math.h>

#define L      128
#define B      64
#define IN_F   512
#define ACT_F  512
#define H      1024
#define G4     4096
#define LSTM_IN 1024

#if defined(__CUDA_ARCH__) && (defined(__CUDA_ARCH_FEAT_SM103_ALL) || defined(__CUDA_ARCH_FEAT_SM100_ALL) || defined(__CUDA_ARCH_SPECIFIC__) || defined(__CUDA_ARCH_FAMILY_SPECIFIC__))
#define HAS_TCGEN05 1
#else
#define HAS_TCGEN05 0
#endif

// ---------------- device scratch ----------------
__device__ float g_gact[(size_t)L * B * G4];
__device__ float g_ginp[B * G4];
__device__ float g_c[B * H];
__device__ __nv_bfloat16 g_Whh_hi[G4 * H];
__device__ __nv_bfloat16 g_Whh_lo[G4 * H];
__device__ __nv_bfloat16 g_h_hi[2][B * H];
__device__ __nv_bfloat16 g_h_lo[2][B * H];
__device__ __nv_bfloat16 g_act_hi[(size_t)L * B * ACT_F];
__device__ __nv_bfloat16 g_act_lo[(size_t)L * B * ACT_F];
__device__ __nv_bfloat16 g_Wact_hi[G4 * ACT_F];
__device__ __nv_bfloat16 g_Wact_lo[G4 * ACT_F];
__device__ unsigned g_bar;

__device__ __forceinline__ float sigm_fast(float x) {
    return __fdividef(1.0f, 1.0f + __expf(-x));
}
__device__ __forceinline__ float tanh_fast(float x) {
    return 1.0f - __fdividef(2.0f, __expf(2.0f * x) + 1.0f);
}

// ---------------- PTX helpers ----------------
__device__ __forceinline__ uint32_t smem_u32(const void* p) {
    uint32_t a;
    asm("{ .reg .u64 t; cvta.to.shared.u64 t, %1; cvt.u32.u64 %0, t; }" : "=r"(a) : "l"(p));
    return a;
}

#define CP_ASYNC16(dst, src) \
    asm volatile("cp.async.cg.shared.global [%0], [%1], 16;" :: "r"((uint32_t)(dst)), "l"(src) : "memory")
#define CP_COMMIT() asm volatile("cp.async.commit_group;" ::: "memory")
#define CP_WAIT(n)  asm volatile("cp.async.wait_group %0;" :: "n"(n) : "memory")
#define CP_MBAR_ARRIVE(addr) \
    asm volatile("cp.async.mbarrier.arrive.noinc.shared.b64 [%0];" :: "r"((uint32_t)(addr)) : "memory")

#define MBARRIER_INIT(addr, cnt) \
    asm volatile("mbarrier.init.shared.b64 [%0], %1;" :: "r"((uint32_t)(addr)), "r"((uint32_t)(cnt)) : "memory")
#define MBARRIER_INVAL(addr) \
    asm volatile("mbarrier.inval.shared.b64 [%0];" :: "r"((uint32_t)(addr)) : "memory")

#define MBARRIER_WAIT_PARITY(mbar_smem_addr, phase_parity) do { \
    uint32_t _mbar = (uint32_t)(mbar_smem_addr); \
    uint32_t _parity = (uint32_t)(phase_parity); \
    uint32_t _done; \
    asm volatile( \
        "{\n\t" \
        ".reg .pred p;\n\t" \
        "mbarrier.try_wait.parity.acquire.cta.shared::cta.b64 p, [%1], %2;\n\t" \
        "selp.b32 %0, 1, 0, p;\n\t" \
        "}" \
        : "=r"(_done) : "r"(_mbar), "r"(_parity) : "memory"); \
    if (!_done) { \
        asm volatile( \
            "{\n\t" \
            ".reg .pred P1;\n\t" \
            "WAIT_LOOP_%=:\n\t" \
            "mbarrier.try_wait.parity.acquire.cta.shared::cta.b64 P1, [%0], %1, 0x989680;\n\t" \
            "@P1 bra.uni WAIT_DONE_%=;\n\t" \
            "bra.uni WAIT_LOOP_%=;\n\t" \
            "WAIT_DONE_%=:\n\t" \
            "}" \
            :: "r"(_mbar), "r"(_parity) : "memory"); \
    } \
} while(0)

#if HAS_TCGEN05
__device__ __forceinline__ uint32_t elect1() {
    uint32_t p;
    asm volatile("{ .reg .pred p; elect.sync _|p, 0xFFFFFFFF; selp.b32 %0, 1, 0, p; }" : "=r"(p));
    return p;
}

#define TCGEN05_ALLOC(smem_result_addr, nCols) \
    asm volatile("tcgen05.alloc.cta_group::1.sync.aligned.shared::cta.b32 [%0], %1;" \
        :: "r"((uint32_t)(smem_result_addr)), "r"((uint32_t)(nCols)) : "memory")
#define TCGEN05_DEALLOC(tmem_addr, nCols) \
    asm volatile("tcgen05.dealloc.cta_group::1.sync.aligned.b32 %0, %1;" :: "r"(tmem_addr), "r"(nCols))
#define TCGEN05_COMMIT(mbar_smem_addr) \
    asm volatile("tcgen05.commit.cta_group::1.mbarrier::arrive::one.shared::cluster.b64 [%0];" \
        :: "r"((uint32_t)(mbar_smem_addr)) : "memory")
#define TCGEN05_FENCE_AFTER() asm volatile("tcgen05.fence::after_thread_sync;" ::: "memory")
#define TCGEN05_FENCE_BEFORE() asm volatile("tcgen05.fence::before_thread_sync;" ::: "memory")
#define TCGEN05_WAIT_LD() asm volatile("tcgen05.wait::ld.sync.aligned;" ::: "memory")
#define FENCE_PROXY_ASYNC_SHARED_CTA() asm volatile("fence.proxy.async.shared::cta;" ::: "memory")

#define TCGEN05_LD_32X32B_X32(r, tmem_addr) \
    asm volatile( \
        "tcgen05.ld.sync.aligned.32x32b.x32.b32 " \
        "{%0, %1, %2, %3, %4, %5, %6, %7, " \
        " %8, %9, %10, %11, %12, %13, %14, %15, " \
        " %16, %17, %18, %19, %20, %21, %22, %23, " \
        " %24, %25, %26, %27, %28, %29, %30, %31}, [%32];" \
        : "=r"((r)[0]),  "=r"((r)[1]),  "=r"((r)[2]),  "=r"((r)[3]), \
          "=r"((r)[4]),  "=r"((r)[5]),  "=r"((r)[6]),  "=r"((r)[7]), \
          "=r"((r)[8]),  "=r"((r)[9]),  "=r"((r)[10]), "=r"((r)[11]), \
          "=r"((r)[12]), "=r"((r)[13]), "=r"((r)[14]), "=r"((r)[15]), \
          "=r"((r)[16]), "=r"((r)[17]), "=r"((r)[18]), "=r"((r)[19]), \
          "=r"((r)[20]), "=r"((r)[21]), "=r"((r)[22]), "=r"((r)[23]), \
          "=r"((r)[24]), "=r"((r)[25]), "=r"((r)[26]), "=r"((r)[27]), \
          "=r"((r)[28]), "=r"((r)[29]), "=r"((r)[30]), "=r"((r)[31]) \
        : "r"(tmem_addr))

__device__ __forceinline__ void mma_bf16_ss(uint32_t d, uint64_t a, uint64_t b,
                                            uint32_t idesc, uint32_t en) {
    asm volatile(
        "{\n\t"
        ".reg .pred p;\n\t"
        "setp.ne.u32 p, %5, 0;\n\t"
        "tcgen05.mma.cta_group::1.kind::f16 [%0], %1, %2, %3, {%4, %4, %4, %4}, p;\n\t"
        "}"
        :: "r"(d), "l"(a), "l"(b), "r"(idesc), "r"(0u), "r"(en) : "memory");
}

static __device__ __forceinline__ uint64_t make_desc(uint32_t base) {
    const uint64_t BASE =
        (uint64_t(2) << 61) | (uint64_t(1) << 46) | (uint64_t(64) << 32) | (uint64_t(1) << 16);
    return BASE | ((uint64_t)(base >> 4) & 0x3FFF);
}
#endif // HAS_TCGEN05

__device__ __forceinline__ uint32_t swz(uint32_t x) { return x ^ ((x >> 3) & 0x70); }

#define MMA_IDESC_N64  0x8100490u
#define MMA_IDESC_N256 0x8400490u

// ---------------- SMEM layout: persistent decoder (3-stage ring) ----------------
#define SM_TMEM   0
#define SM_MB0    8          // mma mbars: 8,16,24
#define SM_LB0    32         // ld mbars:  32,40,48
#define SM_BUF    1024
#define BUF_STRIDE 49152
#define OFF_AHI   0
#define OFF_ALO   16384
#define OFF_BHI   32768
#define OFF_BLO   40960
#define SM_G      (1024 + 3 * BUF_STRIDE)       // 148480
#define SM_GA     (SM_G + 34816)                // 183296
#define SMEM_TOTAL (SM_GA + 34816)              // 218112

// ---------------- SMEM layout: gact_tc kernel ----------------
#define GT_STRIDE 98304
#define GT_AHI    0
#define GT_ALO    16384
#define GT_BHI    32768
#define GT_BLO    65536
#define GT_SMEM_TOTAL (1024 + 2 * GT_STRIDE)

// ---------------- init ----------------
__global__ void init_state_kernel(const float* __restrict__ h0, const float* __restrict__ c0) {
    int i = blockIdx.x * blockDim.x + threadIdx.x;
    if (i == 0) g_bar = 0;
    if (i < B * H) {
        g_c[i] = c0[i];
        float h = h0[i];
        __nv_bfloat16 hi = __float2bfloat16(h);
        g_h_hi[0][i] = hi;
        g_h_lo[0][i] = __float2bfloat16(h - __bfloat162float(hi));
    }
}

// ---------------- combined split kernel (W_hh, act, W_ih-act-part) ----------------
#define N_WHH  (G4 * H)
#define N_ACT  (L * B * ACT_F)
#define N_WACT (G4 * ACT_F)
__global__ void split_all_kernel(const float* __restrict__ Whh,
                                 const float* __restrict__ act,
                                 const float* __restrict__ W_ih) {
    int i = blockIdx.x * blockDim.x + threadIdx.x;
    if (i < N_WHH) {
        float w = Whh[i];
        __nv_bfloat16 hi = __float2bfloat16(w);
        g_Whh_hi[i] = hi;
        g_Whh_lo[i] = __float2bfloat16(w - __bfloat162float(hi));
    } else if (i < N_WHH + N_ACT) {
        int j = i - N_WHH;
        float v = act[j];
        __nv_bfloat16 hi = __float2bfloat16(v);
        g_act_hi[j] = hi;
        g_act_lo[j] = __float2bfloat16(v - __bfloat162float(hi));
    } else if (i < N_WHH + N_ACT + N_WACT) {
        int j = i - N_WHH - N_ACT;
        int n = j >> 9, k = j & 511;
        float w = W_ih[(size_t)n * LSTM_IN + IN_F + k];
        __nv_bfloat16 hi = __float2bfloat16(w);
        g_Wact_hi[j] = hi;
        g_Wact_lo[j] = __float2bfloat16(w - __bfloat162float(hi));
    }
}

// ---------------- ginp (fp32) ----------------
__global__ void ginp_kernel(const float* __restrict__ inp,
                            const float* __restrict__ W_ih,
                            const float* __restrict__ b_ih,
                            const float* __restrict__ b_hh) {
    __shared__ float aT[16][68];
    __shared__ float wT[16][132];
    const int nb0 = blockIdx.x * 128;
    const int tid = threadIdx.x;
    const int tx = tid & 31;
    const int ty = tid >> 5;
    float acc[8][4];
    #pragma unroll
    for (int i = 0; i < 8; i++)
        #pragma unroll
        for (int j = 0; j < 4; j++) acc[i][j] = 0.0f;

    const int lb  = tid >> 2;
    const int lq  = (tid & 3) * 4;
    const int lc  = tid >> 1;
    const int lhf = (tid & 1) * 8;

    for (int k0 = 0; k0 < IN_F; k0 += 16) {
        {
            float4 v = *(const float4*)(inp + lb * IN_F + k0 + lq);
            aT[lq + 0][lb] = v.x; aT[lq + 1][lb] = v.y;
            aT[lq + 2][lb] = v.z; aT[lq + 3][lb] = v.w;
        }
        {
            const float* wp = W_ih + (size_t)(nb0 + lc) * LSTM_IN + k0 + lhf;
            float4 v0 = *(const float4*)(wp);
            float4 v1 = *(const float4*)(wp + 4);
            wT[lhf + 0][lc] = v0.x; wT[lhf + 1][lc] = v0.y;
            wT[lhf + 2][lc] = v0.z; wT[lhf + 3][lc] = v0.w;
            wT[lhf + 4][lc] = v1.x; wT[lhf + 5][lc] = v1.y;
            wT[lhf + 6][lc] = v1.z; wT[lhf + 7][lc] = v1.w;
        }
        __syncthreads();
        #pragma unroll
        for (int kk = 0; kk < 16; kk++) {
            float av[8];
            float4 u0 = *(const float4*)&aT[kk][ty * 8];
            float4 u1 = *(const float4*)&aT[kk][ty * 8 + 4];
            av[0] = u0.x; av[1] = u0.y; av[2] = u0.z; av[3] = u0.w;
            av[4] = u1.x; av[5] = u1.y; av[6] = u1.z; av[7] = u1.w;
            float wv[4];
            #pragma unroll
            for (int jj = 0; jj < 4; jj++) wv[jj] = wT[kk][tx + 32 * jj];
            #pragma unroll
            for (int i = 0; i < 8; i++)
                #pragma unroll
                for (int jj = 0; jj < 4; jj++) acc[i][jj] += av[i] * wv[jj];
        }
        __syncthreads();
    }
    #pragma unroll
    for (int jj = 0; jj < 4; jj++) {
        int n = nb0 + tx + 32 * jj;
        float bb = b_ih[n] + b_hh[n];
        #pragma unroll
        for (int i = 0; i < 8; i++) {
            int b = ty * 8 + i;
            g_ginp[b * G4 + n] = acc[i][jj] + bb;
        }
    }
}

// ---------------- gact_tc ----------------
__global__ void __launch_bounds__(256, 1) gact_tc_kernel(const float* __restrict__ act,
                                                         const float* __restrict__ W_ih) {
    extern __shared__ char smem[];
    const int tid = threadIdx.x;
    const int n0 = blockIdx.x * 256;
    const int r0 = blockIdx.y * 128;

#if HAS_TCGEN05
    uint32_t sb = smem_u32(smem);
    const int wid = tid >> 5;
    const int lid = tid & 31;

    if (wid == 0) TCGEN05_ALLOC(sb + SM_TMEM, 256);
    if (tid == 0) { MBARRIER_INIT(sb + SM_MB0, 1); MBARRIER_INIT(sb + SM_MB0 + 8, 1); }
    __syncthreads();
    uint32_t tmem;
    asm volatile("ld.shared.b32 %0, [%1];" : "=r"(tmem) : "r"(sb + SM_TMEM));

    const char* ahi = (const char*)g_act_hi;
    const char* alo = (const char*)g_act_lo;
    const char* whi = (const char*)g_Wact_hi;
    const char* wlo = (const char*)g_Wact_lo;

    for (int kc = 0; kc < 8; kc++) {
        const int buf = kc & 1;
        if (kc >= 2) {
            uint32_t mb = sb + SM_MB0 + 8 * buf;
            MBARRIER_WAIT_PARITY(mb, ((kc >> 1) - 1) & 1);
        }
        uint32_t base = sb + 1024 + buf * GT_STRIDE;
        #pragma unroll
        for (int i = 0; i < 4; i++) {
            int u = tid + i * 256;
            int row = u >> 3, q = u & 7;
            size_t so = ((size_t)(r0 + row) * 64 + kc * 8 + q) * 16;
            uint32_t d = base + GT_AHI + swz(row * 128 + q * 16);
            CP_ASYNC16(d, ahi + so);
            CP_ASYNC16(d + (GT_ALO - GT_AHI), alo + so);
        }
        #pragma unroll
        for (int i = 0; i < 8; i++) {
            int u = tid + i * 256;
            int row = u >> 3, q = u & 7;
            size_t so = ((size_t)(n0 + row) * 64 + kc * 8 + q) * 16;
            uint32_t d = base + GT_BHI + swz(row * 128 + q * 16);
            CP_ASYNC16(d, whi + so);
            CP_ASYNC16(d + (GT_BLO - GT_BHI), wlo + so);
        }
        CP_COMMIT();
        if (kc >= 1) {
            CP_WAIT(1);
            __syncthreads();
            if (wid == 0) {
                FENCE_PROXY_ASYNC_SHARED_CTA();
                if (elect1()) {
                    int j = kc - 1;
                    uint32_t b2 = sb + 1024 + (j & 1) * GT_STRIDE;
                    uint64_t ah = make_desc(b2 + GT_AHI);
                    uint64_t al = make_desc(b2 + GT_ALO);
                    uint64_t bh = make_desc(b2 + GT_BHI);
                    uint64_t bl = make_desc(b2 + GT_BLO);
                    #pragma unroll
                    for (int k = 0; k < 4; k++)
                        mma_bf16_ss(tmem, ah + 2 * k, bh + 2 * k, MMA_IDESC_N256, !(j == 0 && k == 0));
                    #pragma unroll
                    for (int k = 0; k < 4; k++)
                        mma_bf16_ss(tmem, ah + 2 * k, bl + 2 * k, MMA_IDESC_N256, 1);
                    #pragma unroll
                    for (int k = 0; k < 4; k++)
                        mma_bf16_ss(tmem, al + 2 * k, bh + 2 * k, MMA_IDESC_N256, 1);
                    TCGEN05_COMMIT(sb + SM_MB0 + 8 * (j & 1));
                }
            }
        }
    }
    CP_WAIT(0);
    __syncthreads();
    if (wid == 0) {
        FENCE_PROXY_ASYNC_SHARED_CTA();
        if (elect1()) {
            uint32_t b2 = sb + 1024 + GT_STRIDE;
            uint64_t ah = make_desc(b2 + GT_AHI);
            uint64_t al = make_desc(b2 + GT_ALO);
            uint64_t bh = make_desc(b2 + GT_BHI);
            uint64_t bl = make_desc(b2 + GT_BLO);
            #pragma unroll
            for (int k = 0; k < 4; k++)
                mma_bf16_ss(tmem, ah + 2 * k, bh + 2 * k, MMA_IDESC_N256, 1);
            #pragma unroll
            for (int k = 0; k < 4; k++)
                mma_bf16_ss(tmem, ah + 2 * k, bl + 2 * k, MMA_IDESC_N256, 1);
            #pragma unroll
            for (int k = 0; k < 4; k++)
                mma_bf16_ss(tmem, al + 2 * k, bh + 2 * k, MMA_IDESC_N256, 1);
            TCGEN05_COMMIT(sb + SM_MB0 + 8);
        }
    }

    MBARRIER_WAIT_PARITY(sb + SM_MB0, 1);
    MBARRIER_WAIT_PARITY(sb + SM_MB0 + 8, 1);
    TCGEN05_FENCE_AFTER();

    if (wid < 4) {
        int m = wid * 32 + lid;
        int r = r0 + m;
        int b = r & (B - 1);
        const float4* gi4 = (const float4*)g_ginp;
        float* outp = g_gact + (size_t)r * G4 + n0;
        #pragma unroll
        for (int cb = 0; cb < 8; cb++) {
            uint32_t dr[32];
            TCGEN05_LD_32X32B_X32(dr, tmem + cb * 32);
            TCGEN05_WAIT_LD();
            #pragma unroll
            for (int q = 0; q < 8; q++) {
                float4 g = gi4[b * (G4 / 4) + (n0 >> 2) + cb * 8 + q];
                float4 v;
                v.x = __uint_as_float(dr[q * 4 + 0]) + g.x;
                v.y = __uint_as_float(dr[q * 4 + 1]) + g.y;
                v.z = __uint_as_float(dr[q * 4 + 2]) + g.z;
                v.w = __uint_as_float(dr[q * 4 + 3]) + g.w;
                *(float4*)(outp + cb * 32 + q * 4) = v;
            }
        }
        TCGEN05_FENCE_BEFORE();
    }
    __syncthreads();
    if (tid == 0) { MBARRIER_INVAL(sb + SM_MB0); MBARRIER_INVAL(sb + SM_MB0 + 8); }
    if (wid == 0) TCGEN05_DEALLOC(tmem, 256);
#else
    for (int o = 0; o < 128; o++) {
        int r = r0 + o;
        int n = n0 + tid;
        const float* ap = act + (size_t)r * ACT_F;
        const float* wp = W_ih + (size_t)n * LSTM_IN + IN_F;
        float acc = 0.0f;
        for (int k = 0; k < ACT_F; k++) acc += ap[k] * wp[k];
        g_gact[(size_t)r * G4 + n] = acc + g_ginp[(r & (B - 1)) * G4 + n];
    }
#endif
}

#if HAS_TCGEN05
// ---------------- decoder helpers ----------------
__device__ __forceinline__ void issue_W(uint32_t base, int n, int tid, int j0,
                                        const char* whi, const char* wlo) {
    #pragma unroll
    for (int i = 0; i < 4; i++) {
        int u = tid + i * 256;
        int row = u >> 3, q = u & 7;
        int wrow = ((row >> 5) << 10) + j0 + (row & 31);
        size_t so = ((size_t)wrow * 128 + n * 8 + q) * 16;
        uint32_t d = base + OFF_AHI + swz(row * 128 + q * 16);
        CP_ASYNC16(d, whi + so);
        CP_ASYNC16(d + (OFF_ALO - OFF_AHI), wlo + so);
    }
}
__device__ __forceinline__ void issue_h(uint32_t base, int n, int tid,
                                        const char* hhi, const char* hlo) {
    #pragma unroll
    for (int i = 0; i < 2; i++) {
        int u = tid + i * 256;
        int row = u >> 3, q = u & 7;
        size_t so = ((size_t)row * 128 + n * 8 + q) * 16;
        uint32_t d = base + OFF_BHI + swz(row * 128 + q * 16);
        CP_ASYNC16(d, hhi + so);
        CP_ASYNC16(d + (OFF_BLO - OFF_BHI), hlo + so);
    }
}
__device__ __forceinline__ void issue_GA(uint32_t sb, int t, int tid, int j0) {
    const char* gap = (const char*)(g_gact + (size_t)t * B * G4);
    #pragma unroll
    for (int i = 0; i < 8; i++) {
        int u = tid + i * 256;
        int b = u >> 5;
        int rem = u & 31;
        int g = rem >> 3, qq = rem & 7;
        size_t so = ((size_t)b * 4096 + g * 1024 + j0 + qq * 4) * 4;
        uint32_t d = sb + SM_GA + (b * 136 + g * 32 + qq * 4) * 4;
        CP_ASYNC16(d, gap + so);
    }
    CP_COMMIT();
}
__device__ __forceinline__ void issue_mma(uint32_t tmem, uint32_t base, uint32_t mbar, int first) {
    uint64_t ah = make_desc(base + OFF_AHI);
    uint64_t al = make_desc(base + OFF_ALO);
    uint64_t bh = make_desc(base + OFF_BHI);
    uint64_t bl = make_desc(base + OFF_BLO);
    #pragma unroll
    for (int k = 0; k < 4; k++)
        mma_bf16_ss(tmem, ah + 2 * k, bh + 2 * k, MMA_IDESC_N64, !(first && k == 0));
    #pragma unroll
    for (int k = 0; k < 4; k++)
        mma_bf16_ss(tmem, ah + 2 * k, bl + 2 * k, MMA_IDESC_N64, 1);
    #pragma unroll
    for (int k = 0; k < 4; k++)
        mma_bf16_ss(tmem, al + 2 * k, bh + 2 * k, MMA_IDESC_N64, 1);
    TCGEN05_COMMIT(mbar);
}
#endif

// ---------------- persistent decoder ----------------
__global__ void __launch_bounds__(256, 1) decoder_kernel(const float* __restrict__ Whh,
                                                         float* __restrict__ out) {
    extern __shared__ char smem[];
    uint32_t sb = smem_u32(smem);
    const int tid = threadIdx.x;
    const int wid = tid >> 5;
    const int lid = tid & 31;
    const int j0 = blockIdx.x * 32;

#if HAS_TCGEN05
    if (wid == 0) TCGEN05_ALLOC(sb + SM_TMEM, 128);
    if (tid == 0) {
        MBARRIER_INIT(sb + SM_MB0,      1);
        MBARRIER_INIT(sb + SM_MB0 + 8,  1);
        MBARRIER_INIT(sb + SM_MB0 + 16, 1);
        MBARRIER_INIT(sb + SM_LB0,      256);
        MBARRIER_INIT(sb + SM_LB0 + 8,  256);
        MBARRIER_INIT(sb + SM_LB0 + 16, 256);
    }
    __syncthreads();
    uint32_t tmem;
    asm volatile("ld.shared.b32 %0, [%1];" : "=r"(tmem) : "r"(sb + SM_TMEM));

    const char* whi = (const char*)g_Whh_hi;
    const char* wlo = (const char*)g_Whh_lo;
    uint32_t mc[3] = {0, 0, 0};     // mma-mbar phase counters (all threads)
    uint32_t lc[3] = {0, 0, 0};     // ld-mbar phase counters (warp 0 only)

    // prologue step 0: W for chunks 0,1 + gact slice (no h dependency)
    issue_W(sb + SM_BUF, 0, tid, j0, whi, wlo);
    issue_W(sb + SM_BUF + BUF_STRIDE, 1, tid, j0, whi, wlo);
    issue_GA(sb, 0, tid, j0);
#endif

    for (int t = 0; t < L; t++) {
#if HAS_TCGEN05
        const char* hhi = (const char*)g_h_hi[t & 1];
        const char* hlo = (const char*)g_h_lo[t & 1];

        // h for chunks 0, 1; arrive covers W (issued earlier) + h
        issue_h(sb + SM_BUF, 0, tid, hhi, hlo);
        CP_MBAR_ARRIVE(sb + SM_LB0);
        issue_h(sb + SM_BUF + BUF_STRIDE, 1, tid, hhi, hlo);
        CP_MBAR_ARRIVE(sb + SM_LB0 + 8);

        #pragma unroll
        for (int kc = 0; kc < 16; kc++) {
            const int n = kc + 2;
            if (n <= 15) {
                const int b = n % 3;
                if (n >= 3) {
                    MBARRIER_WAIT_PARITY(sb + SM_MB0 + 8 * b, mc[b] & 1);
                    mc[b]++;
                }
                uint32_t base = sb + SM_BUF + b * BUF_STRIDE;
                issue_W(base, n, tid, j0, whi, wlo);
                issue_h(base, n, tid, hhi, hlo);
                CP_MBAR_ARRIVE(sb + SM_LB0 + 8 * b);
            }
            if (wid == 0) {
                const int bb = kc % 3;
                MBARRIER_WAIT_PARITY(sb + SM_LB0 + 8 * bb, lc[bb] & 1);
                lc[bb]++;
                FENCE_PROXY_ASYNC_SHARED_CTA();
                if (elect1())
                    issue_mma(tmem, sb + SM_BUF + bb * BUF_STRIDE, sb + SM_MB0 + 8 * bb, kc == 0);
            }
        }

        // final completions: chunks 13 (b1), 14 (b2), 15 (b0)
        MBARRIER_WAIT_PARITY(sb + SM_MB0 + 8,  mc[1] & 1); mc[1]++;
        MBARRIER_WAIT_PARITY(sb + SM_MB0 + 16, mc[2] & 1); mc[2]++;
        MBARRIER_WAIT_PARITY(sb + SM_MB0,      mc[0] & 1); mc[0]++;
        TCGEN05_FENCE_AFTER();

        CP_WAIT(0);   // GA group (committed at previous barrier) is done

        // prologue W for next step (buffers free; overlaps drain/epilogue/barrier)
        if (t < L - 1) {
            issue_W(sb + SM_BUF, 0, tid, j0, whi, wlo);
            issue_W(sb + SM_BUF + BUF_STRIDE, 1, tid, j0, whi, wlo);
        }

        // TMEM drain: 8 warps
        {
            int sp = wid & 3;
            int cb = (wid >> 2) * 32;
            uint32_t dr[32];
            TCGEN05_LD_32X32B_X32(dr, tmem + cb);
            TCGEN05_WAIT_LD();
            TCGEN05_FENCE_BEFORE();
            int r = sp * 32 + lid;
            float* sg = (float*)(smem + SM_G) + r * 68 + cb;
            #pragma unroll
            for (int c = 0; c < 32; c++) sg[c] = __uint_as_float(dr[c]);
        }
        __syncthreads();
#else
        {
            float* sg = (float*)(smem + SM_G);
            float* hs = (float*)(smem + SM_BUF);
            const int r   = tid >> 1;
            const int bb0 = (tid & 1) * 32;
            const int wrow = ((r >> 5) << 10) + j0 + (r & 31);
            const float* wp = Whh + (size_t)wrow * H;
            float acc[32];
            #pragma unroll
            for (int i = 0; i < 32; i++) acc[i] = 0.0f;
            for (int kc = 0; kc < 8; kc++) {
                #pragma unroll
                for (int i = 0; i < 32; i++) {
                    int u = tid + i * 256;
                    int b = u >> 7, k = u & 127;
                    int gi = b * H + kc * 128 + k;
                    hs[b * 132 + k] = __bfloat162float(g_h_hi[t & 1][gi]) + __bfloat162float(g_h_lo[t & 1][gi]);
                }
                __syncthreads();
                for (int k = 0; k < 128; k++) {
                    float w = wp[kc * 128 + k];
                    #pragma unroll
                    for (int i = 0; i < 32; i++)
                        acc[i] += w * hs[(bb0 + i) * 132 + k];
                }
                __syncthreads();
            }
            #pragma unroll
            for (int i = 0; i < 32; i++) sg[r * 68 + bb0 + i] = acc[i];
        }
        {
            const float4* gap = (const float4*)(g_gact + (size_t)t * B * G4);
            float* sga = (float*)(smem + SM_GA);
            #pragma unroll
            for (int i = 0; i < 8; i++) {
                int u = tid + i * 256;
                int b = u >> 5;
                int rem = u & 31;
                int g = rem >> 3, qq = rem & 7;
                float4 v = gap[(size_t)b * 1024 + g * 256 + (j0 >> 2) + qq];
                *(float4*)(sga + b * 136 + g * 32 + qq * 4) = v;
            }
        }
        __syncthreads();
#endif

        // ---- LSTM cells ----
        {
            const float* sg  = (const float*)(smem + SM_G);
            const float* sga = (const float*)(smem + SM_GA);
            int b = wid * 8;
            #pragma unroll
            for (int k = 0; k < 8; k++, b++) {
                float s0 = sga[b * 136 +  0 + lid] + sg[( 0 + lid) * 68 + b];
                float s1 = sga[b * 136 + 32 + lid] + sg[(32 + lid) * 68 + b];
                float s2 = sga[b * 136 + 64 + lid] + sg[(64 + lid) * 68 + b];
                float s3 = sga[b * 136 + 96 + lid] + sg[(96 + lid) * 68 + b];
                int gidx = b * H + j0 + lid;
                float c = g_c[gidx];
                float i_ = sigm_fast(s0);
                float f_ = sigm_fast(s1);
                float gg = tanh_fast(s2);
                float o_ = sigm_fast(s3);
                float cn = f_ * c + i_ * gg;
                float hn = o_ * tanh_fast(cn);
                g_c[gidx] = cn;
                out[(size_t)t * B * H + gidx] = hn;
                __nv_bfloat16 hb = __float2bfloat16(hn);
                g_h_hi[(t + 1) & 1][gidx] = hb;
                g_h_lo[(t + 1) & 1][gidx] = __float2bfloat16(hn - __bfloat162float(hb));
            }
        }

        // ---- global step barrier ----
        __threadfence();
        __syncthreads();
#if HAS_TCGEN05
        if (t < L - 1) issue_GA(sb, t + 1, tid, j0);
#endif
        if (tid == 0) {
            atomicAdd(&g_bar, 1u);
            unsigned target = 32u * (unsigned)(t + 1);
            unsigned v;
            do {
                asm volatile("ld.acquire.gpu.global.u32 %0, [%1];" : "=r"(v) : "l"(&g_bar));
            } while (v < target);
        }
        __syncthreads();
    }

#if HAS_TCGEN05
    if (tid == 0) {
        MBARRIER_INVAL(sb + SM_MB0); MBARRIER_INVAL(sb + SM_MB0 + 8); MBARRIER_INVAL(sb + SM_MB0 + 16);
        MBARRIER_INVAL(sb + SM_LB0); MBARRIER_INVAL(sb + SM_LB0 + 8); MBARRIER_INVAL(sb + SM_LB0 + 16);
    }
    if (wid == 0) TCGEN05_DEALLOC(tmem, 128);
#endif
}

// ---------------- tail ----------------
__global__ void tail_kernel(float* __restrict__ out) {
    int idx = blockIdx.x * blockDim.x + threadIdx.x;
    if (idx >= B * H) return;
    out[(size_t)L * B * H + idx]         = out[(size_t)(L - 1) * B * H + idx];
    out[(size_t)L * B * H + B * H + idx] = g_c[idx];
}

extern "C" void kernel_launch(void* const* d_in, const int* in_sizes, int n_in,
                              void* d_out, int out_size) {
    const float* inp  = (const float*)d_in[0];
    const float* act  = (const float*)d_in[1];
    const float* h0   = (const float*)d_in[2];
    const float* c0   = (const float*)d_in[3];
    const float* W_ih = (const float*)d_in[4];
    const float* W_hh = (const float*)d_in[5];
    const float* b_ih = (const float*)d_in[6];
    const float* b_hh = (const float*)d_in[7];
    float* out = (float*)d_out;
    (void)in_sizes; (void)n_in;

    cudaFuncSetAttribute(decoder_kernel, cudaFuncAttributeMaxDynamicSharedMemorySize, SMEM_TOTAL);
    cudaFuncSetAttribute(gact_tc_kernel, cudaFuncAttributeMaxDynamicSharedMemorySize, GT_SMEM_TOTAL);

    init_state_kernel<<<(B * H + 255) / 256, 256>>>(h0, c0);
    split_all_kernel<<<(N_WHH + N_ACT + N_WACT + 255) / 256, 256>>>(W_hh, act, W_ih);
    ginp_kernel<<<32, 256>>>(inp, W_ih, b_ih, b_hh);
    gact_tc_kernel<<<dim3(16, 64), 256, GT_SMEM_TOTAL>>>(act, W_ih);

    decoder_kernel<<<32, 256, SMEM_TOTAL>>>(W_hh, out);

    if (out_size >= L * B * H + 2 * B * H) {
        tail_kernel<<<(B * H + 255) / 256, 256>>>(out);
    }
}